// round 14
// baseline (speedup 1.0000x reference)
#include <cuda_runtime.h>
#include <cuda_fp16.h>
#include <cstdint>

// B=256, S=64, D=512, H=8, DK=DV=64, DFF=2048, IN=32768, OUT=50

// ---------------- device scratch (static, no allocation) ----------------
__device__ __half g_inh  [16384L*512];
__device__ __half g_qkvh [16384L*1536];
__device__ __half g_ctxh [16384L*512];
__device__ __half g_xh   [256L*32768];
__device__ __half g_hh   [256L*2048];
__device__ __half g_yh   [256L*32768];
__device__ __half g_wqkvh[24L*512*64];
__device__ __half g_woh  [512L*512];
__device__ float  g_bqkv [1536];
__device__ float  g_res1 [16384L*512];
__device__ float  g_x    [16384L*512];
__device__ float  g_p4   [16L*256*2048];
__device__ float  g_v2   [256L*32768];
__device__ float  g_wfp  [32768L*64];
__device__ float  g_p6   [64L*256*64];

// ---------------- helpers ----------------
__device__ __forceinline__ uint32_t pack2(float a, float b) {
    __half2 h = __floats2half2_rn(a, b);
    return *reinterpret_cast<uint32_t*>(&h);
}
__device__ __forceinline__ int aoff(int r, int c) {   // A: 64B rows, paired atoms
    return ((r >> 1) << 7) + (((((r & 1) << 2) + c) ^ ((r >> 1) & 7)) << 4);
}
template<int BN>
__device__ __forceinline__ int boff(int k, int c) {   // B: 2*BN B rows
    return k * (2 * BN) + ((((c & ~7) | ((c ^ (k & 7)) & 7))) << 4);
}
__device__ __forceinline__ int foff(int r, int c) {   // 128B rows (attention)
    return (r << 7) + (((c ^ (r & 7)) & 7) << 4);
}
__device__ __forceinline__ void ldsm_x4(uint32_t* r, uint32_t addr) {
    asm volatile("ldmatrix.sync.aligned.m8n8.x4.shared.b16 {%0,%1,%2,%3}, [%4];"
                 : "=r"(r[0]), "=r"(r[1]), "=r"(r[2]), "=r"(r[3]) : "r"(addr));
}
__device__ __forceinline__ void ldsm_x4_t(uint32_t* r, uint32_t addr) {
    asm volatile("ldmatrix.sync.aligned.m8n8.x4.trans.shared.b16 {%0,%1,%2,%3}, [%4];"
                 : "=r"(r[0]), "=r"(r[1]), "=r"(r[2]), "=r"(r[3]) : "r"(addr));
}
__device__ __forceinline__ void mma_fp16(float* d, const uint32_t* a, const uint32_t* b) {
    asm volatile(
        "mma.sync.aligned.m16n8k16.row.col.f32.f16.f16.f32 "
        "{%0,%1,%2,%3},{%4,%5,%6,%7},{%8,%9},{%0,%1,%2,%3};"
        : "+f"(d[0]), "+f"(d[1]), "+f"(d[2]), "+f"(d[3])
        : "r"(a[0]), "r"(a[1]), "r"(a[2]), "r"(a[3]), "r"(b[0]), "r"(b[1]));
}
__device__ __forceinline__ void mma_fp16_2(float* d, const uint32_t* a, uint32_t b0, uint32_t b1) {
    asm volatile(
        "mma.sync.aligned.m16n8k16.row.col.f32.f16.f16.f32 "
        "{%0,%1,%2,%3},{%4,%5,%6,%7},{%8,%9},{%0,%1,%2,%3};"
        : "+f"(d[0]), "+f"(d[1]), "+f"(d[2]), "+f"(d[3])
        : "r"(a[0]), "r"(a[1]), "r"(a[2]), "r"(a[3]), "r"(b0), "r"(b1));
}
__device__ __forceinline__ uint32_t smem_u32(const void* p) {
    uint32_t a;
    asm("{ .reg .u64 t; cvta.to.shared.u64 t, %1; cvt.u32.u64 %0, t; }" : "=r"(a) : "l"(p));
    return a;
}
__device__ __forceinline__ void cp16(uint32_t saddr, const void* g) {
    asm volatile("cp.async.cg.shared.global [%0], [%1], 16;" :: "r"(saddr), "l"(g));
}
#define CP_COMMIT() asm volatile("cp.async.commit_group;" ::: "memory")
#define CP_WAIT2()  asm volatile("cp.async.wait_group 2;" ::: "memory")

// ------------------------------------------------------------------
// cp.async 4-stage all-fp16 GEMM: BM=256, BN=128, BK=32, 512 thr (4x4).
// headStride != 0: B per-head [Hx][512][64] halves; col>>6 = head id.
// ------------------------------------------------------------------
template<bool OH>
__global__ __launch_bounds__(512) void gemma(
    const __half* __restrict__ A, int lda,
    const __half* __restrict__ B, int ldb, int headStride,
    void* __restrict__ Cv, int ldc, int kIters,
    const float* __restrict__ bias,
    const float* __restrict__ resid)
{
    constexpr int ABYTES = 256 * 64;
    constexpr int STAGE  = ABYTES + 32 * 256;  // 24576
    extern __shared__ char smx[];
    const uint32_t sb = smem_u32(smx);

    const int tid = threadIdx.x;
    const int m0 = blockIdx.y * 256;
    const int n0 = blockIdx.x * 128;
    const int warp = tid >> 5, lane = tid & 31;
    const int wm = warp >> 2, wn = warp & 3;
    const int gid = lane >> 2, tg = lane & 3;

    const __half* aptr[2]; uint32_t asto[2];
#pragma unroll
    for (int i = 0; i < 2; i++) {
        int id = tid + i * 512, r = id >> 2, c = id & 3;
        aptr[i] = A + (long)(m0 + r) * lda + c * 8;
        asto[i] = aoff(r, c);
    }
    const int rowStr = headStride ? 64 : ldb;
    const __half* bptr; uint32_t bsto;
    {
        int k = tid >> 4, c = tid & 15;
        int col = n0 + c * 8;
        const __half* bb = headStride ? (B + (long)(col >> 6) * headStride + (col & 63))
                                      : (B + col);
        bptr = bb + (long)k * rowStr;
        bsto = ABYTES + boff<128>(k, c);
    }

    const int aRowL = lane & 15, aChL = lane >> 4;

    float acc[4][4][4];
#pragma unroll
    for (int i = 0; i < 4; i++)
#pragma unroll
        for (int j = 0; j < 4; j++)
#pragma unroll
            for (int l = 0; l < 4; l++) acc[i][j][l] = 0.f;

#pragma unroll
    for (int s = 0; s < 3; s++) {
        const uint32_t st = sb + s * STAGE;
        const long ka = (long)s * 32;
        cp16(st + asto[0], aptr[0] + ka);
        cp16(st + asto[1], aptr[1] + ka);
        cp16(st + bsto, bptr + ka * rowStr);
        CP_COMMIT();
    }

    for (int t = 0; t < kIters; t++) {
        CP_WAIT2();
        __syncthreads();
        if (t + 3 < kIters) {
            const uint32_t st = sb + ((t + 3) & 3) * STAGE;
            const long ka = (long)(t + 3) * 32;
            cp16(st + asto[0], aptr[0] + ka);
            cp16(st + asto[1], aptr[1] + ka);
            cp16(st + bsto, bptr + ka * rowStr);
        }
        CP_COMMIT();
        const uint32_t sa = sb + (t & 3) * STAGE;
        const uint32_t sbB = sa + ABYTES;
#pragma unroll
        for (int kk = 0; kk < 2; kk++) {
            uint32_t af[4][4], bf[2][4];
#pragma unroll
            for (int mt = 0; mt < 4; mt++)
                ldsm_x4(af[mt], sa + aoff(wm * 64 + mt * 16 + aRowL, kk * 2 + aChL));
#pragma unroll
            for (int ntp = 0; ntp < 2; ntp++)
                ldsm_x4_t(bf[ntp], sbB + boff<128>(kk * 16 + aRowL,
                                                   wn * 4 + ntp * 2 + aChL));
#pragma unroll
            for (int mt = 0; mt < 4; mt++)
#pragma unroll
                for (int ntp = 0; ntp < 2; ntp++) {
                    mma_fp16(acc[mt][ntp * 2 + 0], af[mt], &bf[ntp][0]);
                    mma_fp16(acc[mt][ntp * 2 + 1], af[mt], &bf[ntp][2]);
                }
        }
    }

#pragma unroll
    for (int mt = 0; mt < 4; mt++) {
        int r0 = m0 + wm * 64 + mt * 16 + gid;
#pragma unroll
        for (int nt = 0; nt < 4; nt++) {
            int col = n0 + wn * 32 + nt * 8 + tg * 2;
            float2 v0 = make_float2(acc[mt][nt][0], acc[mt][nt][1]);
            float2 v1 = make_float2(acc[mt][nt][2], acc[mt][nt][3]);
            if (bias) {
                float2 bv = *(const float2*)(bias + col);
                v0.x += bv.x; v0.y += bv.y; v1.x += bv.x; v1.y += bv.y;
            }
            if (OH) {
                __half* Ch = (__half*)Cv;
                *(__half2*)(Ch + (long)r0 * ldc + col) = __floats2half2_rn(v0.x, v0.y);
                *(__half2*)(Ch + (long)(r0 + 8) * ldc + col) = __floats2half2_rn(v1.x, v1.y);
            } else {
                float* Cp = (float*)Cv;
                if (resid) {
                    float2 q0 = *(const float2*)(resid + (long)r0 * ldc + col);
                    float2 q1 = *(const float2*)(resid + (long)(r0 + 8) * ldc + col);
                    v0.x += q0.x; v0.y += q0.y; v1.x += q1.x; v1.y += q1.y;
                }
                *(float2*)(Cp + (long)r0 * ldc + col) = v0;
                *(float2*)(Cp + (long)(r0 + 8) * ldc + col) = v1;
            }
        }
    }
}

// ------------------------------------------------------------------
// cp.async 4-stage fp32-B GEMM (W1/W2): BM=256, BN=128, BK=32, 512 thr.
// Stages hold A fp16 + RAW fp32 B; per-tile smem convert -> fp16 swizzled.
// Dynamic smem: 4*32768 + 2*8192 = 147456 B.
// ------------------------------------------------------------------
__global__ __launch_bounds__(512) void gemmW(
    const __half* __restrict__ A, int lda,
    const float* __restrict__ B, int ldb,
    float* __restrict__ C, int ldc,
    int kIters, int kChunk, long cSplit,
    const float* __restrict__ bias,
    const float* __restrict__ resid)
{
    constexpr int ABYTES  = 256 * 64;        // 16384
    constexpr int STAGE   = ABYTES + 16384;  // + raw fp32 B
    constexpr int CONVOFF = 4 * STAGE;       // 131072
    constexpr int CONVSZ  = 32 * 256;        // 8192 fp16 B
    extern __shared__ char smx[];
    const uint32_t sb = smem_u32(smx);

    const int tid = threadIdx.x;
    const int m0 = blockIdx.y * 256;
    const int n0 = blockIdx.x * 128;
    const int k0 = blockIdx.z * kChunk;
    const int warp = tid >> 5, lane = tid & 31;
    const int wm = warp >> 2, wn = warp & 3;
    const int gid = lane >> 2, tg = lane & 3;

    const __half* aptr[2]; uint32_t asto[2];
#pragma unroll
    for (int i = 0; i < 2; i++) {
        int id = tid + i * 512, r = id >> 2, c = id & 3;
        aptr[i] = A + (long)(m0 + r) * lda + k0 + c * 8;
        asto[i] = aoff(r, c);
    }
    const int bk = tid >> 4, bc = tid & 15;
    const float* bptr = B + (long)(k0 + bk) * ldb + n0 + bc * 8;
    const uint32_t brsto = ABYTES + bk * 512 + bc * 32;   // raw fp32 slot
    const uint32_t bcsto = boff<128>(bk, bc);             // conv fp16 slot

    const int aRowL = lane & 15, aChL = lane >> 4;

    float acc[4][4][4];
#pragma unroll
    for (int i = 0; i < 4; i++)
#pragma unroll
        for (int j = 0; j < 4; j++)
#pragma unroll
            for (int l = 0; l < 4; l++) acc[i][j][l] = 0.f;

#pragma unroll
    for (int s = 0; s < 3; s++) {
        const uint32_t st = sb + s * STAGE;
        const long ka = (long)s * 32;
        cp16(st + asto[0], aptr[0] + ka);
        cp16(st + asto[1], aptr[1] + ka);
        cp16(st + brsto, bptr + ka * ldb);
        cp16(st + brsto + 16, bptr + ka * ldb + 4);
        CP_COMMIT();
    }

    for (int t = 0; t < kIters; t++) {
        CP_WAIT2();
        __syncthreads();
        // convert raw fp32 B tile -> fp16 swizzled (double-buffered)
        {
            const char* src = smx + (t & 3) * STAGE + ABYTES + bk * 512 + bc * 32;
            float4 f0 = *(const float4*)(src);
            float4 f1 = *(const float4*)(src + 16);
            uint4 u;
            u.x = pack2(f0.x, f0.y); u.y = pack2(f0.z, f0.w);
            u.z = pack2(f1.x, f1.y); u.w = pack2(f1.z, f1.w);
            *(uint4*)(smx + CONVOFF + (t & 1) * CONVSZ + bcsto) = u;
        }
        if (t + 3 < kIters) {
            const uint32_t st = sb + ((t + 3) & 3) * STAGE;
            const long ka = (long)(t + 3) * 32;
            cp16(st + asto[0], aptr[0] + ka);
            cp16(st + asto[1], aptr[1] + ka);
            cp16(st + brsto, bptr + ka * ldb);
            cp16(st + brsto + 16, bptr + ka * ldb + 4);
        }
        CP_COMMIT();
        __syncthreads();
        const uint32_t sa = sb + (t & 3) * STAGE;
        const uint32_t sbB = sb + CONVOFF + (t & 1) * CONVSZ;
#pragma unroll
        for (int kk = 0; kk < 2; kk++) {
            uint32_t af[4][4], bf[2][4];
#pragma unroll
            for (int mt = 0; mt < 4; mt++)
                ldsm_x4(af[mt], sa + aoff(wm * 64 + mt * 16 + aRowL, kk * 2 + aChL));
#pragma unroll
            for (int ntp = 0; ntp < 2; ntp++)
                ldsm_x4_t(bf[ntp], sbB + boff<128>(kk * 16 + aRowL,
                                                   wn * 4 + ntp * 2 + aChL));
#pragma unroll
            for (int mt = 0; mt < 4; mt++)
#pragma unroll
                for (int ntp = 0; ntp < 2; ntp++) {
                    mma_fp16(acc[mt][ntp * 2 + 0], af[mt], &bf[ntp][0]);
                    mma_fp16(acc[mt][ntp * 2 + 1], af[mt], &bf[ntp][2]);
                }
        }
    }

    float* Cp = C + (long)blockIdx.z * cSplit;
#pragma unroll
    for (int mt = 0; mt < 4; mt++) {
        int r0 = m0 + wm * 64 + mt * 16 + gid;
#pragma unroll
        for (int nt = 0; nt < 4; nt++) {
            int col = n0 + wn * 32 + nt * 8 + tg * 2;
            float2 v0 = make_float2(acc[mt][nt][0], acc[mt][nt][1]);
            float2 v1 = make_float2(acc[mt][nt][2], acc[mt][nt][3]);
            if (bias) {
                float2 bv = *(const float2*)(bias + col);
                v0.x += bv.x; v0.y += bv.y; v1.x += bv.x; v1.y += bv.y;
            }
            if (resid) {
                float2 q0 = *(const float2*)(resid + (long)r0 * ldc + col);
                float2 q1 = *(const float2*)(resid + (long)(r0 + 8) * ldc + col);
                v0.x += q0.x; v0.y += q0.y; v1.x += q1.x; v1.y += q1.y;
            }
            *(float2*)(Cp + (long)r0 * ldc + col) = v0;
            *(float2*)(Cp + (long)(r0 + 8) * ldc + col) = v1;
        }
    }
}

// ------------------------------------------------------------------
// Small fp16 GEMM (Wf): BM=128, BN=64, BK=32, 256 thr (8 warps 4x2).
// ------------------------------------------------------------------
__global__ __launch_bounds__(256) void gemm16s(
    const __half* __restrict__ A, int lda,
    const float* __restrict__ B, int ldb,
    float* __restrict__ C, int ldc,
    int kIters, int kChunk, long cSplit)
{
    constexpr int ABYTES = 128 * 64;
    constexpr int BBYTES = 32 * 128;
    __shared__ char sm[2][ABYTES + BBYTES];

    const int tid = threadIdx.x;
    const int m0 = blockIdx.y * 128;
    const int n0 = blockIdx.x * 64;
    const int k0 = blockIdx.z * kChunk;
    const int warp = tid >> 5, lane = tid & 31;
    const int wm = warp >> 1, wn = warp & 1;
    const int gid = lane >> 2, tg = lane & 3;

    const __half* aptr[2]; int asto[2];
#pragma unroll
    for (int i = 0; i < 2; i++) {
        int id = tid + i * 256, r = id >> 2, c = id & 3;
        aptr[i] = A + (long)(m0 + r) * lda + k0 + c * 8;
        asto[i] = aoff(r, c);
    }
    const float* bptr; int bsto;
    {
        int k = tid >> 3, c = tid & 7;
        bptr = B + (long)(k0 + k) * ldb + n0 + c * 8;
        bsto = ABYTES + boff<64>(k, c);
    }

    const int aRowL = lane & 15, aChL = lane >> 4;
    uint32_t sbase[2] = { smem_u32(&sm[0][0]), smem_u32(&sm[1][0]) };

    float acc[2][4][4];
#pragma unroll
    for (int i = 0; i < 2; i++)
#pragma unroll
        for (int j = 0; j < 4; j++)
#pragma unroll
            for (int l = 0; l < 4; l++) acc[i][j][l] = 0.f;

    uint4 rau[2]; float4 rb0, rb1;
#pragma unroll
    for (int i = 0; i < 2; i++) rau[i] = *(const uint4*)(aptr[i]);
    rb0 = *(const float4*)(bptr);
    rb1 = *(const float4*)(bptr + 4);
#pragma unroll
    for (int i = 0; i < 2; i++) *(uint4*)&sm[0][asto[i]] = rau[i];
    {
        uint4 u;
        u.x = pack2(rb0.x, rb0.y); u.y = pack2(rb0.z, rb0.w);
        u.z = pack2(rb1.x, rb1.y); u.w = pack2(rb1.z, rb1.w);
        *(uint4*)&sm[0][bsto] = u;
    }
    __syncthreads();

    for (int t = 0; t < kIters; t++) {
        if (t + 1 < kIters) {
            const long ka = (long)(t + 1) * 32;
            const long kbb = (long)(t + 1) * 32 * ldb;
#pragma unroll
            for (int i = 0; i < 2; i++) rau[i] = *(const uint4*)(aptr[i] + ka);
            rb0 = *(const float4*)(bptr + kbb);
            rb1 = *(const float4*)(bptr + kbb + 4);
        }
        const uint32_t sa = sbase[t & 1];
        const uint32_t sbB = sbase[t & 1] + ABYTES;
#pragma unroll
        for (int kk = 0; kk < 2; kk++) {
            uint32_t af[2][4], bf[2][4];
#pragma unroll
            for (int mt = 0; mt < 2; mt++)
                ldsm_x4(af[mt], sa + aoff(wm * 32 + mt * 16 + aRowL, kk * 2 + aChL));
#pragma unroll
            for (int ntp = 0; ntp < 2; ntp++)
                ldsm_x4_t(bf[ntp], sbB + boff<64>(kk * 16 + aRowL,
                                                  wn * 4 + ntp * 2 + aChL));
#pragma unroll
            for (int mt = 0; mt < 2; mt++)
#pragma unroll
                for (int ntp = 0; ntp < 2; ntp++) {
                    mma_fp16(acc[mt][ntp * 2 + 0], af[mt], &bf[ntp][0]);
                    mma_fp16(acc[mt][ntp * 2 + 1], af[mt], &bf[ntp][2]);
                }
        }
        if (t + 1 < kIters) {
            char* d = sm[(t + 1) & 1];
#pragma unroll
            for (int i = 0; i < 2; i++) *(uint4*)&d[asto[i]] = rau[i];
            uint4 u;
            u.x = pack2(rb0.x, rb0.y); u.y = pack2(rb0.z, rb0.w);
            u.z = pack2(rb1.x, rb1.y); u.w = pack2(rb1.z, rb1.w);
            *(uint4*)&d[bsto] = u;
            __syncthreads();
        }
    }

    float* Cp = C + (long)blockIdx.z * cSplit;
#pragma unroll
    for (int mt = 0; mt < 2; mt++) {
        int r0 = m0 + wm * 32 + mt * 16 + gid;
#pragma unroll
        for (int nt = 0; nt < 4; nt++) {
            int col = n0 + wn * 32 + nt * 8 + tg * 2;
            *(float2*)(Cp + (long)r0 * ldc + col) =
                make_float2(acc[mt][nt][0], acc[mt][nt][1]);
            *(float2*)(Cp + (long)(r0 + 8) * ldc + col) =
                make_float2(acc[mt][nt][2], acc[mt][nt][3]);
        }
    }
}

// ------------------------------------------------------------------
// MMA attention per (b,h): QKV packed [16384,1536]; fp16 in/out, fp32 acc.
// ------------------------------------------------------------------
__global__ __launch_bounds__(128) void attn_mma(
    const __half* __restrict__ QKV, __half* __restrict__ Ctx)
{
    __shared__ __align__(16) char sq[64 * 128], sk[64 * 128], sv[64 * 128];
    const int tid = threadIdx.x;
    const int w = tid >> 5, lane = tid & 31;
    const int gid = lane >> 2, tg = lane & 3;
    const int b = blockIdx.x >> 3, h = blockIdx.x & 7;
    const long base = (long)(b * 64) * 1536 + h * 64;

#pragma unroll
    for (int i = 0; i < 4; i++) {
        int id = tid + i * 128, r = id >> 3, c = id & 7;
        int so = foff(r, c);
        const long go = base + (long)r * 1536 + c * 8;
        *(uint4*)(sq + so) = *(const uint4*)(QKV + go);
        *(uint4*)(sk + so) = *(const uint4*)(QKV + go + 512);
        *(uint4*)(sv + so) = *(const uint4*)(QKV + go + 1024);
    }
    __syncthreads();

    const uint32_t sqb = smem_u32(sq), skb = smem_u32(sk), svb = smem_u32(sv);
    const int rowL = lane & 15, chL = lane >> 4;

    float sacc[8][4];
#pragma unroll
    for (int j = 0; j < 8; j++)
#pragma unroll
        for (int l = 0; l < 4; l++) sacc[j][l] = 0.f;
#pragma unroll
    for (int kk = 0; kk < 4; kk++) {
        uint32_t a[4];
        ldsm_x4(a, sqb + foff(w * 16 + rowL, kk * 2 + chL));
#pragma unroll
        for (int g = 0; g < 4; g++) {
            uint32_t bk[4];
            ldsm_x4(bk, skb + foff(g * 16 + rowL, kk * 2 + chL));
            mma_fp16_2(sacc[g * 2 + 0], a, bk[0], bk[2]);
            mma_fp16_2(sacc[g * 2 + 1], a, bk[1], bk[3]);
        }
    }

    float mx0 = -1e30f, mx1 = -1e30f;
#pragma unroll
    for (int j = 0; j < 8; j++) {
#pragma unroll
        for (int l = 0; l < 4; l++) sacc[j][l] *= 0.125f;
        mx0 = fmaxf(mx0, fmaxf(sacc[j][0], sacc[j][1]));
        mx1 = fmaxf(mx1, fmaxf(sacc[j][2], sacc[j][3]));
    }
#pragma unroll
    for (int o = 1; o < 4; o <<= 1) {
        mx0 = fmaxf(mx0, __shfl_xor_sync(~0u, mx0, o));
        mx1 = fmaxf(mx1, __shfl_xor_sync(~0u, mx1, o));
    }
    float s0 = 0.f, s1 = 0.f;
#pragma unroll
    for (int j = 0; j < 8; j++) {
        sacc[j][0] = __expf(sacc[j][0] - mx0);
        sacc[j][1] = __expf(sacc[j][1] - mx0);
        sacc[j][2] = __expf(sacc[j][2] - mx1);
        sacc[j][3] = __expf(sacc[j][3] - mx1);
        s0 += sacc[j][0] + sacc[j][1];
        s1 += sacc[j][2] + sacc[j][3];
    }
#pragma unroll
    for (int o = 1; o < 4; o <<= 1) {
        s0 += __shfl_xor_sync(~0u, s0, o);
        s1 += __shfl_xor_sync(~0u, s1, o);
    }
    const float r0 = 1.f / s0, r1 = 1.f / s1;

    uint32_t ap[4][4];
#pragma unroll
    for (int kk = 0; kk < 4; kk++) {
        ap[kk][0] = pack2(sacc[kk * 2][0], sacc[kk * 2][1]);
        ap[kk][1] = pack2(sacc[kk * 2][2], sacc[kk * 2][3]);
        ap[kk][2] = pack2(sacc[kk * 2 + 1][0], sacc[kk * 2 + 1][1]);
        ap[kk][3] = pack2(sacc[kk * 2 + 1][2], sacc[kk * 2 + 1][3]);
    }

    float cacc[8][4];
#pragma unroll
    for (int j = 0; j < 8; j++)
#pragma unroll
        for (int l = 0; l < 4; l++) cacc[j][l] = 0.f;
#pragma unroll
    for (int kk = 0; kk < 4; kk++) {
#pragma unroll
        for (int g = 0; g < 4; g++) {
            uint32_t bv[4];
            ldsm_x4_t(bv, svb + foff(kk * 16 + rowL, g * 2 + chL));
            mma_fp16_2(cacc[g * 2 + 0], ap[kk], bv[0], bv[1]);
            mma_fp16_2(cacc[g * 2 + 1], ap[kk], bv[2], bv[3]);
        }
    }

    const long orow0 = (long)(b * 64 + w * 16 + gid) * 512 + h * 64;
    const long orow1 = orow0 + 8 * 512;
#pragma unroll
    for (int nt = 0; nt < 8; nt++) {
        int col = nt * 8 + tg * 2;
        *(__half2*)(Ctx + orow0 + col) = __floats2half2_rn(cacc[nt][0] * r0, cacc[nt][1] * r0);
        *(__half2*)(Ctx + orow1 + col) = __floats2half2_rn(cacc[nt][2] * r1, cacc[nt][3] * r1);
    }
}

// ---------------- small prep / post kernels ----------------
__global__ void cvt_f2h(const float* __restrict__ in, __half* __restrict__ out)
{
    int idx = blockIdx.x * 256 + threadIdx.x;
    float4 f = ((const float4*)in)[idx];
    __half2* o = (__half2*)out + idx * 2;
    o[0] = __floats2half2_rn(f.x, f.y);
    o[1] = __floats2half2_rn(f.z, f.w);
}

__global__ void cat_bias_k(const float* bq, const float* bk, const float* bv, float* o)
{
    int i = blockIdx.x * 256 + threadIdx.x;   // < 1536
    o[i] = (i < 512) ? bq[i] : (i < 1024 ? bk[i - 512] : bv[i - 1024]);
}

__global__ __launch_bounds__(256) void ln512_dual(
    const float* __restrict__ in, float* __restrict__ out, __half* __restrict__ outh,
    const float* __restrict__ gam, const float* __restrict__ bet)
{
    const int row = blockIdx.x * 8 + (threadIdx.x >> 5);
    const int lane = threadIdx.x & 31;
    const float* p = in + (long)row * 512;
    float v[16], s = 0.f, s2 = 0.f;
#pragma unroll
    for (int i = 0; i < 16; i++) {
        v[i] = p[lane + 32 * i]; s += v[i]; s2 = fmaf(v[i], v[i], s2);
    }
#pragma unroll
    for (int o = 16; o > 0; o >>= 1) {
        s += __shfl_xor_sync(~0u, s, o); s2 += __shfl_xor_sync(~0u, s2, o);
    }
    float mu = s * (1.f / 512.f);
    float rsg = rsqrtf(s2 * (1.f / 512.f) - mu * mu + 1e-5f);
    float* q = out + (long)row * 512;
    __half* qh = outh + (long)row * 512;
#pragma unroll
    for (int i = 0; i < 16; i++) {
        int c = lane + 32 * i;
        float r = (v[i] - mu) * rsg * gam[c] + bet[c];
        q[c] = r;
        qh[c] = __float2half_rn(r);
    }
}

__global__ __launch_bounds__(1024) void ln32k_h(
    const float* __restrict__ in, __half* __restrict__ out,
    const float* __restrict__ gam, const float* __restrict__ bet)
{
    __shared__ float rs1[32], rs2[32], stat[2];
    const int row = blockIdx.x;
    const float* p = in + (long)row * 32768;
    float s = 0.f, s2 = 0.f;
    for (int i = threadIdx.x; i < 32768; i += 1024) {
        float v = p[i]; s += v; s2 = fmaf(v, v, s2);
    }
#pragma unroll
    for (int o = 16; o > 0; o >>= 1) {
        s += __shfl_xor_sync(~0u, s, o); s2 += __shfl_xor_sync(~0u, s2, o);
    }
    if ((threadIdx.x & 31) == 0) { rs1[threadIdx.x >> 5] = s; rs2[threadIdx.x >> 5] = s2; }
    __syncthreads();
    if (threadIdx.x < 32) {
        s = rs1[threadIdx.x]; s2 = rs2[threadIdx.x];
#pragma unroll
        for (int o = 16; o > 0; o >>= 1) {
            s += __shfl_xor_sync(~0u, s, o); s2 += __shfl_xor_sync(~0u, s2, o);
        }
        if (threadIdx.x == 0) {
            float mu = s * (1.f / 32768.f);
            stat[0] = mu; stat[1] = rsqrtf(s2 * (1.f / 32768.f) - mu * mu + 1e-5f);
        }
    }
    __syncthreads();
    float mu = stat[0], rsg = stat[1];
    __half* q = out + (long)row * 32768;
    for (int i = threadIdx.x; i < 32768; i += 1024)
        q[i] = __float2half_rn((p[i] - mu) * rsg * gam[i] + bet[i]);
}

__global__ void reduce16_relu_h(const float* __restrict__ part,
                                const float* __restrict__ b1, __half* __restrict__ out)
{
    int idx = blockIdx.x * 256 + threadIdx.x;  // < 524288
    float s = 0.f;
#pragma unroll
    for (int z = 0; z < 16; z++) s += part[(long)z * 524288 + idx];
    s += b1[idx & 2047];
    out[idx] = __float2half_rn(fmaxf(s, 0.f));
}

__global__ void reduce_out_k(const float* __restrict__ part,
                             const float* __restrict__ bf, float* __restrict__ out)
{
    int idx = blockIdx.x * 256 + threadIdx.x;
    if (idx >= 12800) return;
    int m = idx / 50, j = idx % 50;
    float s = bf[j];
#pragma unroll
    for (int z = 0; z < 64; z++) s += part[(long)z * 16384 + m * 64 + j];
    out[idx] = s;
}

__global__ void pad_wf_k(const float* __restrict__ Wf, float* __restrict__ Wfp)
{
    int idx = blockIdx.x * 256 + threadIdx.x;  // < 32768*64
    int k = idx >> 6, j = idx & 63;
    Wfp[idx] = (j < 50) ? Wf[k * 50 + j] : 0.f;
}

// ------------------------------------------------------------------
extern "C" void kernel_launch(void* const* d_in, const int* in_sizes, int n_in,
                              void* d_out, int out_size)
{
    const float* inputs = (const float*)d_in[0];
    const float* Wq = (const float*)d_in[1];  const float* bq = (const float*)d_in[2];
    const float* Wk = (const float*)d_in[3];  const float* bk = (const float*)d_in[4];
    const float* Wv = (const float*)d_in[5];  const float* bv = (const float*)d_in[6];
    const float* Wo = (const float*)d_in[7];  const float* bo = (const float*)d_in[8];
    const float* ln1g = (const float*)d_in[9];  const float* ln1b = (const float*)d_in[10];
    const float* W1 = (const float*)d_in[11]; const float* b1 = (const float*)d_in[12];
    const float* W2 = (const float*)d_in[13]; const float* b2 = (const float*)d_in[14];
    const float* ln2g = (const float*)d_in[15]; const float* ln2b = (const float*)d_in[16];
    const float* Wf = (const float*)d_in[17]; const float* bf = (const float*)d_in[18];
    float* out = (float*)d_out;

    __half *inh, *qkvh, *ctxh, *xh, *hh, *yh, *wqkvh, *woh;
    float *bqkv, *res1, *x, *p4, *v2, *wfp, *p6;
    cudaGetSymbolAddress((void**)&inh, g_inh);
    cudaGetSymbolAddress((void**)&qkvh, g_qkvh);
    cudaGetSymbolAddress((void**)&ctxh, g_ctxh);
    cudaGetSymbolAddress((void**)&xh, g_xh);
    cudaGetSymbolAddress((void**)&hh, g_hh);
    cudaGetSymbolAddress((void**)&yh, g_yh);
    cudaGetSymbolAddress((void**)&wqkvh, g_wqkvh);
    cudaGetSymbolAddress((void**)&woh, g_woh);
    cudaGetSymbolAddress((void**)&bqkv, g_bqkv);
    cudaGetSymbolAddress((void**)&res1, g_res1);
    cudaGetSymbolAddress((void**)&x, g_x);
    cudaGetSymbolAddress((void**)&p4, g_p4);
    cudaGetSymbolAddress((void**)&v2, g_v2);
    cudaGetSymbolAddress((void**)&wfp, g_wfp);
    cudaGetSymbolAddress((void**)&p6, g_p6);

    constexpr int GSMEM = 4 * 24576;           // 96 KB
    constexpr int WSMEM = 4 * 32768 + 2 * 8192; // 147456 B
    cudaFuncSetAttribute(gemma<true>, cudaFuncAttributeMaxDynamicSharedMemorySize, GSMEM);
    cudaFuncSetAttribute(gemma<false>, cudaFuncAttributeMaxDynamicSharedMemorySize, GSMEM);
    cudaFuncSetAttribute(gemmW, cudaFuncAttributeMaxDynamicSharedMemorySize, WSMEM);

    // independent prep
    pad_wf_k<<<8192, 256>>>(Wf, wfp);
    cvt_f2h<<<8192, 256>>>(inputs, inh);
    cvt_f2h<<<256, 256>>>(Wq, wqkvh);               // heads 0-7
    cvt_f2h<<<256, 256>>>(Wk, wqkvh + 8L*512*64);   // heads 8-15
    cvt_f2h<<<256, 256>>>(Wv, wqkvh + 16L*512*64);  // heads 16-23
    cvt_f2h<<<256, 256>>>(Wo, woh);
    cat_bias_k<<<6, 256>>>(bq, bk, bv, bqkv);

    // fused QKV -> qkvh [16384, 1536]
    gemma<true><<<dim3(12, 64), 512, GSMEM>>>(inh, 512, wqkvh, 0, 32768,
                                              qkvh, 1536, 16, bqkv, nullptr);

    // MMA attention
    attn_mma<<<2048, 128>>>(qkvh, ctxh);

    // output projection + bias + residual(inputs) -> fp32
    gemma<false><<<dim3(4, 64), 512, GSMEM>>>(ctxh, 512, woh, 512, 0,
                                              res1, 512, 16, bo, inputs);

    // LN1 -> x (fp32) + xh (fp16)
    ln512_dual<<<2048, 256>>>(res1, x, xh, ln1g, ln1b);

    // h = relu(x @ W1 + b1): split-K 16, cp.async pipelined fp32-B
    gemmW<<<dim3(16, 1, 16), 512, WSMEM>>>(xh, 32768, W1, 2048,
                                           p4, 2048, 64, 2048, 524288,
                                           nullptr, nullptr);
    reduce16_relu_h<<<2048, 256>>>(p4, b1, hh);

    // v2 = h @ W2 + b2 + x -> fp32
    gemmW<<<dim3(256, 1, 1), 512, WSMEM>>>(hh, 2048, W2, 32768,
                                           v2, 32768, 64, 0, 0, b2, x);

    // LN2 -> yh fp16
    ln32k_h<<<256, 1024>>>(v2, yh, ln2g, ln2b);

    // logits: y @ wfp split-K 64
    gemm16s<<<dim3(1, 2, 64), 256>>>(yh, 32768, wfp, 64, p6, 64, 16, 512, 16384);
    reduce_out_k<<<50, 256>>>(p6, bf, out);
}

// round 15
// speedup vs baseline: 1.0741x; 1.0741x over previous
#include <cuda_runtime.h>
#include <cuda_fp16.h>
#include <cstdint>

// B=256, S=64, D=512, H=8, DK=DV=64, DFF=2048, IN=32768, OUT=50

// ---------------- device scratch (static, no allocation) ----------------
__device__ __half g_inh  [16384L*512];
__device__ __half g_qkvh [16384L*1536];
__device__ __half g_ctxh [16384L*512];
__device__ __half g_xh   [256L*32768];
__device__ __half g_hh   [256L*2048];
__device__ __half g_yh   [256L*32768];
__device__ __half g_wqkvh[24L*512*64];
__device__ __half g_woh  [512L*512];
__device__ float  g_bqkv [1536];
__device__ float  g_res1 [16384L*512];
__device__ float  g_x    [16384L*512];
__device__ float  g_p4   [16L*256*2048];
__device__ float  g_v2   [256L*32768];
__device__ float  g_wfp  [32768L*64];
__device__ float  g_p6   [64L*256*64];

// ---------------- helpers ----------------
__device__ __forceinline__ uint32_t pack2(float a, float b) {
    __half2 h = __floats2half2_rn(a, b);
    return *reinterpret_cast<uint32_t*>(&h);
}
__device__ __forceinline__ int aoff(int r, int c) {   // A: 64B rows, paired atoms
    return ((r >> 1) << 7) + (((((r & 1) << 2) + c) ^ ((r >> 1) & 7)) << 4);
}
template<int BN>
__device__ __forceinline__ int boff(int k, int c) {   // B: 2*BN B rows
    return k * (2 * BN) + ((((c & ~7) | ((c ^ (k & 7)) & 7))) << 4);
}
__device__ __forceinline__ int foff(int r, int c) {   // 128B rows (attention)
    return (r << 7) + (((c ^ (r & 7)) & 7) << 4);
}
__device__ __forceinline__ void ldsm_x4(uint32_t* r, uint32_t addr) {
    asm volatile("ldmatrix.sync.aligned.m8n8.x4.shared.b16 {%0,%1,%2,%3}, [%4];"
                 : "=r"(r[0]), "=r"(r[1]), "=r"(r[2]), "=r"(r[3]) : "r"(addr));
}
__device__ __forceinline__ void ldsm_x4_t(uint32_t* r, uint32_t addr) {
    asm volatile("ldmatrix.sync.aligned.m8n8.x4.trans.shared.b16 {%0,%1,%2,%3}, [%4];"
                 : "=r"(r[0]), "=r"(r[1]), "=r"(r[2]), "=r"(r[3]) : "r"(addr));
}
__device__ __forceinline__ void mma_fp16(float* d, const uint32_t* a, const uint32_t* b) {
    asm volatile(
        "mma.sync.aligned.m16n8k16.row.col.f32.f16.f16.f32 "
        "{%0,%1,%2,%3},{%4,%5,%6,%7},{%8,%9},{%0,%1,%2,%3};"
        : "+f"(d[0]), "+f"(d[1]), "+f"(d[2]), "+f"(d[3])
        : "r"(a[0]), "r"(a[1]), "r"(a[2]), "r"(a[3]), "r"(b[0]), "r"(b[1]));
}
__device__ __forceinline__ void mma_fp16_2(float* d, const uint32_t* a, uint32_t b0, uint32_t b1) {
    asm volatile(
        "mma.sync.aligned.m16n8k16.row.col.f32.f16.f16.f32 "
        "{%0,%1,%2,%3},{%4,%5,%6,%7},{%8,%9},{%0,%1,%2,%3};"
        : "+f"(d[0]), "+f"(d[1]), "+f"(d[2]), "+f"(d[3])
        : "r"(a[0]), "r"(a[1]), "r"(a[2]), "r"(a[3]), "r"(b0), "r"(b1));
}
__device__ __forceinline__ uint32_t smem_u32(const void* p) {
    uint32_t a;
    asm("{ .reg .u64 t; cvta.to.shared.u64 t, %1; cvt.u32.u64 %0, t; }" : "=r"(a) : "l"(p));
    return a;
}
__device__ __forceinline__ void cp16(uint32_t saddr, const void* g) {
    asm volatile("cp.async.cg.shared.global [%0], [%1], 16;" :: "r"(saddr), "l"(g));
}
#define CP_COMMIT() asm volatile("cp.async.commit_group;" ::: "memory")
#define CP_WAIT2()  asm volatile("cp.async.wait_group 2;" ::: "memory")

// ------------------------------------------------------------------
// 2-CTA/SM GEMM: BM=128, BN=128, BK=32, 256 thr (8 warps, 2x4),
// 4-stage cp.async. BF32: B is raw fp32, converted per-tile in smem
// (dual barrier, hidden by co-resident CTA). OH: fp16 output.
// headStride != 0 (fp16 B only): per-head [Hx][512][64].
// ------------------------------------------------------------------
template<bool BF32, bool OH>
__global__ __launch_bounds__(256, 2) void gemm2c(
    const __half* __restrict__ A, int lda,
    const void* __restrict__ Bv, int ldb, int headStride,
    void* __restrict__ Cv, int ldc,
    int kIters, int kChunk, long cSplit,
    const float* __restrict__ bias,
    const float* __restrict__ resid)
{
    constexpr int ABYTES = 128 * 64;                  // 8192
    constexpr int BRAW   = BF32 ? 16384 : 8192;
    constexpr int STAGE  = ABYTES + BRAW;
    constexpr int CONVOFF = 4 * STAGE;
    constexpr int CONVSZ  = 8192;
    extern __shared__ char smx[];
    const uint32_t sb = smem_u32(smx);

    const int tid = threadIdx.x;
    const int m0 = blockIdx.y * 128;
    const int n0 = blockIdx.x * 128;
    const int k0 = blockIdx.z * kChunk;
    const int warp = tid >> 5, lane = tid & 31;
    const int wm = warp >> 2, wn = warp & 3;          // 2 x 4
    const int gid = lane >> 2, tg = lane & 3;

    // A cp.async: 8 KB = 512 chunks, 2 per thread
    const __half* aptr[2]; uint32_t asto[2];
#pragma unroll
    for (int i = 0; i < 2; i++) {
        int id = tid + i * 256, r = id >> 2, c = id & 3;
        aptr[i] = A + (long)(m0 + r) * lda + k0 + c * 8;
        asto[i] = aoff(r, c);
    }

    // B staging
    const __half* bp16[2]; uint32_t bs16[2];
    const float*  bp32[4]; uint32_t bs32[4];
    int rowStr = ldb;
    if (!BF32) {
        const __half* Bh = (const __half*)Bv;
        rowStr = headStride ? 64 : ldb;
#pragma unroll
        for (int i = 0; i < 2; i++) {
            int id = tid + i * 256, k = id >> 4, c = id & 15;
            int col = n0 + c * 8;
            const __half* bb = headStride ? (Bh + (long)(col >> 6) * headStride + (col & 63))
                                          : (Bh + col);
            bp16[i] = bb + (long)(k0 + k) * rowStr;
            bs16[i] = ABYTES + boff<128>(k, c);
        }
    } else {
        const float* Bf = (const float*)Bv;
#pragma unroll
        for (int i = 0; i < 4; i++) {
            int id = tid + i * 256, k = id >> 5, c = id & 31;
            bp32[i] = Bf + (long)(k0 + k) * ldb + n0 + c * 4;
            bs32[i] = ABYTES + k * 512 + c * 16;
        }
    }

    const int aRowL = lane & 15, aChL = lane >> 4;

    float acc[4][4][4];
#pragma unroll
    for (int i = 0; i < 4; i++)
#pragma unroll
        for (int j = 0; j < 4; j++)
#pragma unroll
            for (int l = 0; l < 4; l++) acc[i][j][l] = 0.f;

    // prologue: stages 0..2
#pragma unroll
    for (int s = 0; s < 3; s++) {
        const uint32_t st = sb + s * STAGE;
        const long ka = (long)s * 32;
        cp16(st + asto[0], aptr[0] + ka);
        cp16(st + asto[1], aptr[1] + ka);
        if (!BF32) {
            cp16(st + bs16[0], bp16[0] + ka * rowStr);
            cp16(st + bs16[1], bp16[1] + ka * rowStr);
        } else {
#pragma unroll
            for (int i = 0; i < 4; i++) cp16(st + bs32[i], bp32[i] + ka * ldb);
        }
        CP_COMMIT();
    }

    for (int t = 0; t < kIters; t++) {
        CP_WAIT2();
        __syncthreads();
        if (BF32) {
            // convert raw fp32 B tile -> fp16 swizzled conv buffer (t&1)
#pragma unroll
            for (int i = 0; i < 2; i++) {
                int id = tid + i * 256, k = id >> 4, c = id & 15;
                const char* src = smx + (t & 3) * STAGE + ABYTES + k * 512 + c * 32;
                float4 f0 = *(const float4*)(src);
                float4 f1 = *(const float4*)(src + 16);
                uint4 u;
                u.x = pack2(f0.x, f0.y); u.y = pack2(f0.z, f0.w);
                u.z = pack2(f1.x, f1.y); u.w = pack2(f1.z, f1.w);
                *(uint4*)(smx + CONVOFF + (t & 1) * CONVSZ + boff<128>(k, c)) = u;
            }
        }
        if (t + 3 < kIters) {
            const uint32_t st = sb + ((t + 3) & 3) * STAGE;
            const long ka = (long)(t + 3) * 32;
            cp16(st + asto[0], aptr[0] + ka);
            cp16(st + asto[1], aptr[1] + ka);
            if (!BF32) {
                cp16(st + bs16[0], bp16[0] + ka * rowStr);
                cp16(st + bs16[1], bp16[1] + ka * rowStr);
            } else {
#pragma unroll
                for (int i = 0; i < 4; i++) cp16(st + bs32[i], bp32[i] + ka * ldb);
            }
        }
        CP_COMMIT();
        if (BF32) __syncthreads();
        const uint32_t sa = sb + (t & 3) * STAGE;
        const uint32_t sbB = BF32 ? (sb + CONVOFF + (t & 1) * CONVSZ) : (sa + ABYTES);
#pragma unroll
        for (int kk = 0; kk < 2; kk++) {
            uint32_t af[4][4], bf[2][4];
#pragma unroll
            for (int mt = 0; mt < 4; mt++)
                ldsm_x4(af[mt], sa + aoff(wm * 64 + mt * 16 + aRowL, kk * 2 + aChL));
#pragma unroll
            for (int ntp = 0; ntp < 2; ntp++)
                ldsm_x4_t(bf[ntp], sbB + boff<128>(kk * 16 + aRowL,
                                                   wn * 4 + ntp * 2 + aChL));
#pragma unroll
            for (int mt = 0; mt < 4; mt++)
#pragma unroll
                for (int ntp = 0; ntp < 2; ntp++) {
                    mma_fp16(acc[mt][ntp * 2 + 0], af[mt], &bf[ntp][0]);
                    mma_fp16(acc[mt][ntp * 2 + 1], af[mt], &bf[ntp][2]);
                }
        }
    }

    // epilogue
#pragma unroll
    for (int mt = 0; mt < 4; mt++) {
        int r0 = m0 + wm * 64 + mt * 16 + gid;
#pragma unroll
        for (int nt = 0; nt < 4; nt++) {
            int col = n0 + wn * 32 + nt * 8 + tg * 2;
            float2 v0 = make_float2(acc[mt][nt][0], acc[mt][nt][1]);
            float2 v1 = make_float2(acc[mt][nt][2], acc[mt][nt][3]);
            if (bias) {
                float2 bv = *(const float2*)(bias + col);
                v0.x += bv.x; v0.y += bv.y; v1.x += bv.x; v1.y += bv.y;
            }
            if (OH) {
                __half* Ch = (__half*)Cv;
                *(__half2*)(Ch + (long)r0 * ldc + col) = __floats2half2_rn(v0.x, v0.y);
                *(__half2*)(Ch + (long)(r0 + 8) * ldc + col) = __floats2half2_rn(v1.x, v1.y);
            } else {
                float* Cp = (float*)Cv + (long)blockIdx.z * cSplit;
                if (resid) {
                    float2 q0 = *(const float2*)(resid + (long)r0 * ldc + col);
                    float2 q1 = *(const float2*)(resid + (long)(r0 + 8) * ldc + col);
                    v0.x += q0.x; v0.y += q0.y; v1.x += q1.x; v1.y += q1.y;
                }
                *(float2*)(Cp + (long)r0 * ldc + col) = v0;
                *(float2*)(Cp + (long)(r0 + 8) * ldc + col) = v1;
            }
        }
    }
}

// ------------------------------------------------------------------
// Small fp16 GEMM (Wf): BM=128, BN=64, BK=32, 256 thr (8 warps 4x2).
// ------------------------------------------------------------------
__global__ __launch_bounds__(256) void gemm16s(
    const __half* __restrict__ A, int lda,
    const float* __restrict__ B, int ldb,
    float* __restrict__ C, int ldc,
    int kIters, int kChunk, long cSplit)
{
    constexpr int ABYTES = 128 * 64;
    constexpr int BBYTES = 32 * 128;
    __shared__ char sm[2][ABYTES + BBYTES];

    const int tid = threadIdx.x;
    const int m0 = blockIdx.y * 128;
    const int n0 = blockIdx.x * 64;
    const int k0 = blockIdx.z * kChunk;
    const int warp = tid >> 5, lane = tid & 31;
    const int wm = warp >> 1, wn = warp & 1;
    const int gid = lane >> 2, tg = lane & 3;

    const __half* aptr[2]; int asto[2];
#pragma unroll
    for (int i = 0; i < 2; i++) {
        int id = tid + i * 256, r = id >> 2, c = id & 3;
        aptr[i] = A + (long)(m0 + r) * lda + k0 + c * 8;
        asto[i] = aoff(r, c);
    }
    const float* bptr; int bsto;
    {
        int k = tid >> 3, c = tid & 7;
        bptr = B + (long)(k0 + k) * ldb + n0 + c * 8;
        bsto = ABYTES + boff<64>(k, c);
    }

    const int aRowL = lane & 15, aChL = lane >> 4;
    uint32_t sbase[2] = { smem_u32(&sm[0][0]), smem_u32(&sm[1][0]) };

    float acc[2][4][4];
#pragma unroll
    for (int i = 0; i < 2; i++)
#pragma unroll
        for (int j = 0; j < 4; j++)
#pragma unroll
            for (int l = 0; l < 4; l++) acc[i][j][l] = 0.f;

    uint4 rau[2]; float4 rb0, rb1;
#pragma unroll
    for (int i = 0; i < 2; i++) rau[i] = *(const uint4*)(aptr[i]);
    rb0 = *(const float4*)(bptr);
    rb1 = *(const float4*)(bptr + 4);
#pragma unroll
    for (int i = 0; i < 2; i++) *(uint4*)&sm[0][asto[i]] = rau[i];
    {
        uint4 u;
        u.x = pack2(rb0.x, rb0.y); u.y = pack2(rb0.z, rb0.w);
        u.z = pack2(rb1.x, rb1.y); u.w = pack2(rb1.z, rb1.w);
        *(uint4*)&sm[0][bsto] = u;
    }
    __syncthreads();

    for (int t = 0; t < kIters; t++) {
        if (t + 1 < kIters) {
            const long ka = (long)(t + 1) * 32;
            const long kbb = (long)(t + 1) * 32 * ldb;
#pragma unroll
            for (int i = 0; i < 2; i++) rau[i] = *(const uint4*)(aptr[i] + ka);
            rb0 = *(const float4*)(bptr + kbb);
            rb1 = *(const float4*)(bptr + kbb + 4);
        }
        const uint32_t sa = sbase[t & 1];
        const uint32_t sbB = sbase[t & 1] + ABYTES;
#pragma unroll
        for (int kk = 0; kk < 2; kk++) {
            uint32_t af[2][4], bf[2][4];
#pragma unroll
            for (int mt = 0; mt < 2; mt++)
                ldsm_x4(af[mt], sa + aoff(wm * 32 + mt * 16 + aRowL, kk * 2 + aChL));
#pragma unroll
            for (int ntp = 0; ntp < 2; ntp++)
                ldsm_x4_t(bf[ntp], sbB + boff<64>(kk * 16 + aRowL,
                                                  wn * 4 + ntp * 2 + aChL));
#pragma unroll
            for (int mt = 0; mt < 2; mt++)
#pragma unroll
                for (int ntp = 0; ntp < 2; ntp++) {
                    mma_fp16(acc[mt][ntp * 2 + 0], af[mt], &bf[ntp][0]);
                    mma_fp16(acc[mt][ntp * 2 + 1], af[mt], &bf[ntp][2]);
                }
        }
        if (t + 1 < kIters) {
            char* d = sm[(t + 1) & 1];
#pragma unroll
            for (int i = 0; i < 2; i++) *(uint4*)&d[asto[i]] = rau[i];
            uint4 u;
            u.x = pack2(rb0.x, rb0.y); u.y = pack2(rb0.z, rb0.w);
            u.z = pack2(rb1.x, rb1.y); u.w = pack2(rb1.z, rb1.w);
            *(uint4*)&d[bsto] = u;
            __syncthreads();
        }
    }

    float* Cp = C + (long)blockIdx.z * cSplit;
#pragma unroll
    for (int mt = 0; mt < 2; mt++) {
        int r0 = m0 + wm * 32 + mt * 16 + gid;
#pragma unroll
        for (int nt = 0; nt < 4; nt++) {
            int col = n0 + wn * 32 + nt * 8 + tg * 2;
            *(float2*)(Cp + (long)r0 * ldc + col) =
                make_float2(acc[mt][nt][0], acc[mt][nt][1]);
            *(float2*)(Cp + (long)(r0 + 8) * ldc + col) =
                make_float2(acc[mt][nt][2], acc[mt][nt][3]);
        }
    }
}

// ------------------------------------------------------------------
// MMA attention per (b,h): QKV packed [16384,1536]; fp16 in/out, fp32 acc.
// ------------------------------------------------------------------
__global__ __launch_bounds__(128) void attn_mma(
    const __half* __restrict__ QKV, __half* __restrict__ Ctx)
{
    __shared__ __align__(16) char sq[64 * 128], sk[64 * 128], sv[64 * 128];
    const int tid = threadIdx.x;
    const int w = tid >> 5, lane = tid & 31;
    const int gid = lane >> 2, tg = lane & 3;
    const int b = blockIdx.x >> 3, h = blockIdx.x & 7;
    const long base = (long)(b * 64) * 1536 + h * 64;

#pragma unroll
    for (int i = 0; i < 4; i++) {
        int id = tid + i * 128, r = id >> 3, c = id & 7;
        int so = foff(r, c);
        const long go = base + (long)r * 1536 + c * 8;
        *(uint4*)(sq + so) = *(const uint4*)(QKV + go);
        *(uint4*)(sk + so) = *(const uint4*)(QKV + go + 512);
        *(uint4*)(sv + so) = *(const uint4*)(QKV + go + 1024);
    }
    __syncthreads();

    const uint32_t sqb = smem_u32(sq), skb = smem_u32(sk), svb = smem_u32(sv);
    const int rowL = lane & 15, chL = lane >> 4;

    float sacc[8][4];
#pragma unroll
    for (int j = 0; j < 8; j++)
#pragma unroll
        for (int l = 0; l < 4; l++) sacc[j][l] = 0.f;
#pragma unroll
    for (int kk = 0; kk < 4; kk++) {
        uint32_t a[4];
        ldsm_x4(a, sqb + foff(w * 16 + rowL, kk * 2 + chL));
#pragma unroll
        for (int g = 0; g < 4; g++) {
            uint32_t bk[4];
            ldsm_x4(bk, skb + foff(g * 16 + rowL, kk * 2 + chL));
            mma_fp16_2(sacc[g * 2 + 0], a, bk[0], bk[2]);
            mma_fp16_2(sacc[g * 2 + 1], a, bk[1], bk[3]);
        }
    }

    float mx0 = -1e30f, mx1 = -1e30f;
#pragma unroll
    for (int j = 0; j < 8; j++) {
#pragma unroll
        for (int l = 0; l < 4; l++) sacc[j][l] *= 0.125f;
        mx0 = fmaxf(mx0, fmaxf(sacc[j][0], sacc[j][1]));
        mx1 = fmaxf(mx1, fmaxf(sacc[j][2], sacc[j][3]));
    }
#pragma unroll
    for (int o = 1; o < 4; o <<= 1) {
        mx0 = fmaxf(mx0, __shfl_xor_sync(~0u, mx0, o));
        mx1 = fmaxf(mx1, __shfl_xor_sync(~0u, mx1, o));
    }
    float s0 = 0.f, s1 = 0.f;
#pragma unroll
    for (int j = 0; j < 8; j++) {
        sacc[j][0] = __expf(sacc[j][0] - mx0);
        sacc[j][1] = __expf(sacc[j][1] - mx0);
        sacc[j][2] = __expf(sacc[j][2] - mx1);
        sacc[j][3] = __expf(sacc[j][3] - mx1);
        s0 += sacc[j][0] + sacc[j][1];
        s1 += sacc[j][2] + sacc[j][3];
    }
#pragma unroll
    for (int o = 1; o < 4; o <<= 1) {
        s0 += __shfl_xor_sync(~0u, s0, o);
        s1 += __shfl_xor_sync(~0u, s1, o);
    }
    const float r0 = 1.f / s0, r1 = 1.f / s1;

    uint32_t ap[4][4];
#pragma unroll
    for (int kk = 0; kk < 4; kk++) {
        ap[kk][0] = pack2(sacc[kk * 2][0], sacc[kk * 2][1]);
        ap[kk][1] = pack2(sacc[kk * 2][2], sacc[kk * 2][3]);
        ap[kk][2] = pack2(sacc[kk * 2 + 1][0], sacc[kk * 2 + 1][1]);
        ap[kk][3] = pack2(sacc[kk * 2 + 1][2], sacc[kk * 2 + 1][3]);
    }

    float cacc[8][4];
#pragma unroll
    for (int j = 0; j < 8; j++)
#pragma unroll
        for (int l = 0; l < 4; l++) cacc[j][l] = 0.f;
#pragma unroll
    for (int kk = 0; kk < 4; kk++) {
#pragma unroll
        for (int g = 0; g < 4; g++) {
            uint32_t bv[4];
            ldsm_x4_t(bv, svb + foff(kk * 16 + rowL, g * 2 + chL));
            mma_fp16_2(cacc[g * 2 + 0], ap[kk], bv[0], bv[1]);
            mma_fp16_2(cacc[g * 2 + 1], ap[kk], bv[2], bv[3]);
        }
    }

    const long orow0 = (long)(b * 64 + w * 16 + gid) * 512 + h * 64;
    const long orow1 = orow0 + 8 * 512;
#pragma unroll
    for (int nt = 0; nt < 8; nt++) {
        int col = nt * 8 + tg * 2;
        *(__half2*)(Ctx + orow0 + col) = __floats2half2_rn(cacc[nt][0] * r0, cacc[nt][1] * r0);
        *(__half2*)(Ctx + orow1 + col) = __floats2half2_rn(cacc[nt][2] * r1, cacc[nt][3] * r1);
    }
}

// ---------------- small prep / post kernels ----------------
__global__ void cvt_f2h(const float* __restrict__ in, __half* __restrict__ out)
{
    int idx = blockIdx.x * 256 + threadIdx.x;
    float4 f = ((const float4*)in)[idx];
    __half2* o = (__half2*)out + idx * 2;
    o[0] = __floats2half2_rn(f.x, f.y);
    o[1] = __floats2half2_rn(f.z, f.w);
}

__global__ void cat_bias_k(const float* bq, const float* bk, const float* bv, float* o)
{
    int i = blockIdx.x * 256 + threadIdx.x;   // < 1536
    o[i] = (i < 512) ? bq[i] : (i < 1024 ? bk[i - 512] : bv[i - 1024]);
}

__global__ __launch_bounds__(256) void ln512_dual(
    const float* __restrict__ in, float* __restrict__ out, __half* __restrict__ outh,
    const float* __restrict__ gam, const float* __restrict__ bet)
{
    const int row = blockIdx.x * 8 + (threadIdx.x >> 5);
    const int lane = threadIdx.x & 31;
    const float* p = in + (long)row * 512;
    float v[16], s = 0.f, s2 = 0.f;
#pragma unroll
    for (int i = 0; i < 16; i++) {
        v[i] = p[lane + 32 * i]; s += v[i]; s2 = fmaf(v[i], v[i], s2);
    }
#pragma unroll
    for (int o = 16; o > 0; o >>= 1) {
        s += __shfl_xor_sync(~0u, s, o); s2 += __shfl_xor_sync(~0u, s2, o);
    }
    float mu = s * (1.f / 512.f);
    float rsg = rsqrtf(s2 * (1.f / 512.f) - mu * mu + 1e-5f);
    float* q = out + (long)row * 512;
    __half* qh = outh + (long)row * 512;
#pragma unroll
    for (int i = 0; i < 16; i++) {
        int c = lane + 32 * i;
        float r = (v[i] - mu) * rsg * gam[c] + bet[c];
        q[c] = r;
        qh[c] = __float2half_rn(r);
    }
}

__global__ __launch_bounds__(1024) void ln32k_h(
    const float* __restrict__ in, __half* __restrict__ out,
    const float* __restrict__ gam, const float* __restrict__ bet)
{
    __shared__ float rs1[32], rs2[32], stat[2];
    const int row = blockIdx.x;
    const float* p = in + (long)row * 32768;
    float s = 0.f, s2 = 0.f;
    for (int i = threadIdx.x; i < 32768; i += 1024) {
        float v = p[i]; s += v; s2 = fmaf(v, v, s2);
    }
#pragma unroll
    for (int o = 16; o > 0; o >>= 1) {
        s += __shfl_xor_sync(~0u, s, o); s2 += __shfl_xor_sync(~0u, s2, o);
    }
    if ((threadIdx.x & 31) == 0) { rs1[threadIdx.x >> 5] = s; rs2[threadIdx.x >> 5] = s2; }
    __syncthreads();
    if (threadIdx.x < 32) {
        s = rs1[threadIdx.x]; s2 = rs2[threadIdx.x];
#pragma unroll
        for (int o = 16; o > 0; o >>= 1) {
            s += __shfl_xor_sync(~0u, s, o); s2 += __shfl_xor_sync(~0u, s2, o);
        }
        if (threadIdx.x == 0) {
            float mu = s * (1.f / 32768.f);
            stat[0] = mu; stat[1] = rsqrtf(s2 * (1.f / 32768.f) - mu * mu + 1e-5f);
        }
    }
    __syncthreads();
    float mu = stat[0], rsg = stat[1];
    __half* q = out + (long)row * 32768;
    for (int i = threadIdx.x; i < 32768; i += 1024)
        q[i] = __float2half_rn((p[i] - mu) * rsg * gam[i] + bet[i]);
}

__global__ void reduce16_relu_h(const float* __restrict__ part,
                                const float* __restrict__ b1, __half* __restrict__ out)
{
    int idx = blockIdx.x * 256 + threadIdx.x;  // < 524288
    float s = 0.f;
#pragma unroll
    for (int z = 0; z < 16; z++) s += part[(long)z * 524288 + idx];
    s += b1[idx & 2047];
    out[idx] = __float2half_rn(fmaxf(s, 0.f));
}

__global__ void reduce_out_k(const float* __restrict__ part,
                             const float* __restrict__ bf, float* __restrict__ out)
{
    int idx = blockIdx.x * 256 + threadIdx.x;
    if (idx >= 12800) return;
    int m = idx / 50, j = idx % 50;
    float s = bf[j];
#pragma unroll
    for (int z = 0; z < 64; z++) s += part[(long)z * 16384 + m * 64 + j];
    out[idx] = s;
}

__global__ void pad_wf_k(const float* __restrict__ Wf, float* __restrict__ Wfp)
{
    int idx = blockIdx.x * 256 + threadIdx.x;  // < 32768*64
    int k = idx >> 6, j = idx & 63;
    Wfp[idx] = (j < 50) ? Wf[k * 50 + j] : 0.f;
}

// ------------------------------------------------------------------
extern "C" void kernel_launch(void* const* d_in, const int* in_sizes, int n_in,
                              void* d_out, int out_size)
{
    const float* inputs = (const float*)d_in[0];
    const float* Wq = (const float*)d_in[1];  const float* bq = (const float*)d_in[2];
    const float* Wk = (const float*)d_in[3];  const float* bk = (const float*)d_in[4];
    const float* Wv = (const float*)d_in[5];  const float* bv = (const float*)d_in[6];
    const float* Wo = (const float*)d_in[7];  const float* bo = (const float*)d_in[8];
    const float* ln1g = (const float*)d_in[9];  const float* ln1b = (const float*)d_in[10];
    const float* W1 = (const float*)d_in[11]; const float* b1 = (const float*)d_in[12];
    const float* W2 = (const float*)d_in[13]; const float* b2 = (const float*)d_in[14];
    const float* ln2g = (const float*)d_in[15]; const float* ln2b = (const float*)d_in[16];
    const float* Wf = (const float*)d_in[17]; const float* bf = (const float*)d_in[18];
    float* out = (float*)d_out;

    __half *inh, *qkvh, *ctxh, *xh, *hh, *yh, *wqkvh, *woh;
    float *bqkv, *res1, *x, *p4, *v2, *wfp, *p6;
    cudaGetSymbolAddress((void**)&inh, g_inh);
    cudaGetSymbolAddress((void**)&qkvh, g_qkvh);
    cudaGetSymbolAddress((void**)&ctxh, g_ctxh);
    cudaGetSymbolAddress((void**)&xh, g_xh);
    cudaGetSymbolAddress((void**)&hh, g_hh);
    cudaGetSymbolAddress((void**)&yh, g_yh);
    cudaGetSymbolAddress((void**)&wqkvh, g_wqkvh);
    cudaGetSymbolAddress((void**)&woh, g_woh);
    cudaGetSymbolAddress((void**)&bqkv, g_bqkv);
    cudaGetSymbolAddress((void**)&res1, g_res1);
    cudaGetSymbolAddress((void**)&x, g_x);
    cudaGetSymbolAddress((void**)&p4, g_p4);
    cudaGetSymbolAddress((void**)&v2, g_v2);
    cudaGetSymbolAddress((void**)&wfp, g_wfp);
    cudaGetSymbolAddress((void**)&p6, g_p6);

    constexpr int SM16 = 4 * 16384;              // 64 KB  (fp16 B)
    constexpr int SM32 = 4 * 24576 + 2 * 8192;   // 114688 (fp32 B)
    cudaFuncSetAttribute((const void*)gemm2c<false, true>,
                         cudaFuncAttributeMaxDynamicSharedMemorySize, SM16);
    cudaFuncSetAttribute((const void*)gemm2c<false, false>,
                         cudaFuncAttributeMaxDynamicSharedMemorySize, SM16);
    cudaFuncSetAttribute((const void*)gemm2c<true, false>,
                         cudaFuncAttributeMaxDynamicSharedMemorySize, SM32);

    // independent prep
    pad_wf_k<<<8192, 256>>>(Wf, wfp);
    cvt_f2h<<<8192, 256>>>(inputs, inh);
    cvt_f2h<<<256, 256>>>(Wq, wqkvh);               // heads 0-7
    cvt_f2h<<<256, 256>>>(Wk, wqkvh + 8L*512*64);   // heads 8-15
    cvt_f2h<<<256, 256>>>(Wv, wqkvh + 16L*512*64);  // heads 16-23
    cvt_f2h<<<256, 256>>>(Wo, woh);
    cat_bias_k<<<6, 256>>>(bq, bk, bv, bqkv);

    // fused QKV -> qkvh [16384, 1536]
    gemm2c<false, true><<<dim3(12, 128), 256, SM16>>>(
        inh, 512, wqkvh, 0, 32768, qkvh, 1536, 16, 0, 0, bqkv, nullptr);

    // MMA attention
    attn_mma<<<2048, 128>>>(qkvh, ctxh);

    // output projection + bias + residual(inputs) -> fp32
    gemm2c<false, false><<<dim3(4, 128), 256, SM16>>>(
        ctxh, 512, woh, 512, 0, res1, 512, 16, 0, 0, bo, inputs);

    // LN1 -> x (fp32) + xh (fp16)
    ln512_dual<<<2048, 256>>>(res1, x, xh, ln1g, ln1b);

    // h = relu(x @ W1 + b1): split-K 16
    gemm2c<true, false><<<dim3(16, 2, 16), 256, SM32>>>(
        xh, 32768, W1, 2048, 0, p4, 2048, 64, 2048, 524288, nullptr, nullptr);
    reduce16_relu_h<<<2048, 256>>>(p4, b1, hh);

    // v2 = h @ W2 + b2 + x -> fp32
    gemm2c<true, false><<<dim3(256, 2, 1), 256, SM32>>>(
        hh, 2048, W2, 32768, 0, v2, 32768, 64, 0, 0, b2, x);

    // LN2 -> yh fp16
    ln32k_h<<<256, 1024>>>(v2, yh, ln2g, ln2b);

    // logits: y @ wfp split-K 64
    gemm16s<<<dim3(1, 2, 64), 256>>>(yh, 32768, wfp, 64, p6, 64, 16, 512, 16384);
    reduce_out_k<<<50, 256>>>(p6, bf, out);
}

// round 16
// speedup vs baseline: 1.1307x; 1.0527x over previous
#include <cuda_runtime.h>
#include <cuda_fp16.h>
#include <cstdint>

// B=256, S=64, D=512, H=8, DK=DV=64, DFF=2048, IN=32768, OUT=50

// ---------------- device scratch (static, no allocation) ----------------
__device__ __half g_inh  [16384L*512];
__device__ __half g_qkvh [16384L*1536];
__device__ __half g_ctxh [16384L*512];
__device__ __half g_xh   [256L*32768];
__device__ __half g_hh   [256L*2048];
__device__ __half g_yh   [256L*32768];
__device__ __half g_wqkvh[24L*512*64];
__device__ __half g_woh  [512L*512];
__device__ __half g_wfph [32768L*64];
__device__ float  g_bqkv [1536];
__device__ float  g_res1 [16384L*512];
__device__ float  g_p4   [8L*256*2048];
__device__ float  g_v2   [256L*32768];
__device__ float  g_p6   [64L*256*64];

// ---------------- helpers ----------------
__device__ __forceinline__ uint32_t pack2(float a, float b) {
    __half2 h = __floats2half2_rn(a, b);
    return *reinterpret_cast<uint32_t*>(&h);
}
__device__ __forceinline__ int aoff(int r, int c) {   // 64B rows, paired atoms
    return ((r >> 1) << 7) + (((((r & 1) << 2) + c) ^ ((r >> 1) & 7)) << 4);
}
template<int BN>
__device__ __forceinline__ int boff(int k, int c) {   // 2*BN B rows
    return k * (2 * BN) + ((((c & ~7) | ((c ^ (k & 7)) & 7))) << 4);
}
__device__ __forceinline__ int foff(int r, int c) {   // 128B rows
    return (r << 7) + (((c ^ (r & 7)) & 7) << 4);
}
__device__ __forceinline__ void ldsm_x4(uint32_t* r, uint32_t addr) {
    asm volatile("ldmatrix.sync.aligned.m8n8.x4.shared.b16 {%0,%1,%2,%3}, [%4];"
                 : "=r"(r[0]), "=r"(r[1]), "=r"(r[2]), "=r"(r[3]) : "r"(addr));
}
__device__ __forceinline__ void ldsm_x4_t(uint32_t* r, uint32_t addr) {
    asm volatile("ldmatrix.sync.aligned.m8n8.x4.trans.shared.b16 {%0,%1,%2,%3}, [%4];"
                 : "=r"(r[0]), "=r"(r[1]), "=r"(r[2]), "=r"(r[3]) : "r"(addr));
}
__device__ __forceinline__ void mma_fp16(float* d, const uint32_t* a, const uint32_t* b) {
    asm volatile(
        "mma.sync.aligned.m16n8k16.row.col.f32.f16.f16.f32 "
        "{%0,%1,%2,%3},{%4,%5,%6,%7},{%8,%9},{%0,%1,%2,%3};"
        : "+f"(d[0]), "+f"(d[1]), "+f"(d[2]), "+f"(d[3])
        : "r"(a[0]), "r"(a[1]), "r"(a[2]), "r"(a[3]), "r"(b[0]), "r"(b[1]));
}
__device__ __forceinline__ void mma_fp16_2(float* d, const uint32_t* a, uint32_t b0, uint32_t b1) {
    asm volatile(
        "mma.sync.aligned.m16n8k16.row.col.f32.f16.f16.f32 "
        "{%0,%1,%2,%3},{%4,%5,%6,%7},{%8,%9},{%0,%1,%2,%3};"
        : "+f"(d[0]), "+f"(d[1]), "+f"(d[2]), "+f"(d[3])
        : "r"(a[0]), "r"(a[1]), "r"(a[2]), "r"(a[3]), "r"(b0), "r"(b1));
}
__device__ __forceinline__ uint32_t smem_u32(const void* p) {
    uint32_t a;
    asm("{ .reg .u64 t; cvta.to.shared.u64 t, %1; cvt.u32.u64 %0, t; }" : "=r"(a) : "l"(p));
    return a;
}
__device__ __forceinline__ void cp16(uint32_t saddr, const void* g) {
    asm volatile("cp.async.cg.shared.global [%0], [%1], 16;" :: "r"(saddr), "l"(g));
}
#define CP_COMMIT() asm volatile("cp.async.commit_group;" ::: "memory")
#define CP_WAIT1()  asm volatile("cp.async.wait_group 1;" ::: "memory")
#define CP_WAIT2()  asm volatile("cp.async.wait_group 2;" ::: "memory")

// ------------------------------------------------------------------
// fp16-B GEMM, BK=64, 3-stage cp.async, BM=128 BN=128, 256 thr (2x4),
// 2 CTAs/SM. A rows 128B (foff). OH: fp16 out, else fp32 (+bias/resid).
// ------------------------------------------------------------------
template<bool OH>
__global__ __launch_bounds__(256, 2) void gemmf64(
    const __half* __restrict__ A, int lda,
    const __half* __restrict__ B, int ldb, int headStride,
    void* __restrict__ Cv, int ldc, int kIters,
    const float* __restrict__ bias,
    const float* __restrict__ resid)
{
    constexpr int ABYTES = 128 * 128;     // 16384
    constexpr int STAGE  = ABYTES + 64 * 256;  // +16384 = 32768
    extern __shared__ char smx[];
    const uint32_t sb = smem_u32(smx);

    const int tid = threadIdx.x;
    const int m0 = blockIdx.y * 128;
    const int n0 = blockIdx.x * 128;
    const int warp = tid >> 5, lane = tid & 31;
    const int wm = warp >> 2, wn = warp & 3;
    const int gid = lane >> 2, tg = lane & 3;

    const __half* aptr[4]; uint32_t asto[4];
#pragma unroll
    for (int i = 0; i < 4; i++) {
        int id = tid + i * 256, r = id >> 3, c = id & 7;
        aptr[i] = A + (long)(m0 + r) * lda + c * 8;
        asto[i] = foff(r, c);
    }
    const int rowStr = headStride ? 64 : ldb;
    const __half* bptr[4]; uint32_t bsto[4];
#pragma unroll
    for (int i = 0; i < 4; i++) {
        int id = tid + i * 256, k = id >> 4, c = id & 15;
        int col = n0 + c * 8;
        const __half* bb = headStride ? (B + (long)(col >> 6) * headStride + (col & 63))
                                      : (B + col);
        bptr[i] = bb + (long)k * rowStr;
        bsto[i] = ABYTES + boff<128>(k, c);
    }

    const int rowL = lane & 15, chL = lane >> 4;

    float acc[4][4][4];
#pragma unroll
    for (int i = 0; i < 4; i++)
#pragma unroll
        for (int j = 0; j < 4; j++)
#pragma unroll
            for (int l = 0; l < 4; l++) acc[i][j][l] = 0.f;

#pragma unroll
    for (int s = 0; s < 2; s++) {
        const uint32_t st = sb + s * STAGE;
        const long ka = (long)s * 64;
#pragma unroll
        for (int i = 0; i < 4; i++) cp16(st + asto[i], aptr[i] + ka);
#pragma unroll
        for (int i = 0; i < 4; i++) cp16(st + bsto[i], bptr[i] + ka * rowStr);
        CP_COMMIT();
    }

    for (int t = 0; t < kIters; t++) {
        CP_WAIT1();
        __syncthreads();
        if (t + 2 < kIters) {
            const uint32_t st = sb + ((t + 2) % 3) * STAGE;
            const long ka = (long)(t + 2) * 64;
#pragma unroll
            for (int i = 0; i < 4; i++) cp16(st + asto[i], aptr[i] + ka);
#pragma unroll
            for (int i = 0; i < 4; i++) cp16(st + bsto[i], bptr[i] + ka * rowStr);
        }
        CP_COMMIT();
        const uint32_t sa = sb + (t % 3) * STAGE;
        const uint32_t sbB = sa + ABYTES;
#pragma unroll
        for (int kk = 0; kk < 4; kk++) {
            uint32_t af[4][4], bf[2][4];
#pragma unroll
            for (int mt = 0; mt < 4; mt++)
                ldsm_x4(af[mt], sa + foff(wm * 64 + mt * 16 + rowL, kk * 2 + chL));
#pragma unroll
            for (int ntp = 0; ntp < 2; ntp++)
                ldsm_x4_t(bf[ntp], sbB + boff<128>(kk * 16 + rowL,
                                                   wn * 4 + ntp * 2 + chL));
#pragma unroll
            for (int mt = 0; mt < 4; mt++)
#pragma unroll
                for (int ntp = 0; ntp < 2; ntp++) {
                    mma_fp16(acc[mt][ntp * 2 + 0], af[mt], &bf[ntp][0]);
                    mma_fp16(acc[mt][ntp * 2 + 1], af[mt], &bf[ntp][2]);
                }
        }
    }

#pragma unroll
    for (int mt = 0; mt < 4; mt++) {
        int r0 = m0 + wm * 64 + mt * 16 + gid;
#pragma unroll
        for (int nt = 0; nt < 4; nt++) {
            int col = n0 + wn * 32 + nt * 8 + tg * 2;
            float2 v0 = make_float2(acc[mt][nt][0], acc[mt][nt][1]);
            float2 v1 = make_float2(acc[mt][nt][2], acc[mt][nt][3]);
            if (bias) {
                float2 bv = *(const float2*)(bias + col);
                v0.x += bv.x; v0.y += bv.y; v1.x += bv.x; v1.y += bv.y;
            }
            if (OH) {
                __half* Ch = (__half*)Cv;
                *(__half2*)(Ch + (long)r0 * ldc + col) = __floats2half2_rn(v0.x, v0.y);
                *(__half2*)(Ch + (long)(r0 + 8) * ldc + col) = __floats2half2_rn(v1.x, v1.y);
            } else {
                float* Cp = (float*)Cv;
                if (resid) {
                    float2 q0 = *(const float2*)(resid + (long)r0 * ldc + col);
                    float2 q1 = *(const float2*)(resid + (long)(r0 + 8) * ldc + col);
                    v0.x += q0.x; v0.y += q0.y; v1.x += q1.x; v1.y += q1.y;
                }
                *(float2*)(Cp + (long)r0 * ldc + col) = v0;
                *(float2*)(Cp + (long)(r0 + 8) * ldc + col) = v1;
            }
        }
    }
}

// ------------------------------------------------------------------
// fp32-B GEMM (W1/W2): BM=128 BN=128 BK=32, 4-stage cp.async, smem
// convert, 256 thr, 2 CTAs/SM. residh: optional fp16 residual.
// ------------------------------------------------------------------
__global__ __launch_bounds__(256, 2) void gemmw(
    const __half* __restrict__ A, int lda,
    const float* __restrict__ B, int ldb,
    float* __restrict__ C, int ldc,
    int kIters, int kChunk, long cSplit,
    const float* __restrict__ bias,
    const __half* __restrict__ residh)
{
    constexpr int ABYTES = 128 * 64;       // 8192
    constexpr int STAGE  = ABYTES + 16384; // 24576
    constexpr int CONVOFF = 4 * STAGE;     // 98304
    constexpr int CONVSZ  = 8192;
    extern __shared__ char smx[];
    const uint32_t sb = smem_u32(smx);

    const int tid = threadIdx.x;
    const int m0 = blockIdx.y * 128;
    const int n0 = blockIdx.x * 128;
    const int k0 = blockIdx.z * kChunk;
    const int warp = tid >> 5, lane = tid & 31;
    const int wm = warp >> 2, wn = warp & 3;
    const int gid = lane >> 2, tg = lane & 3;

    const __half* aptr[2]; uint32_t asto[2];
#pragma unroll
    for (int i = 0; i < 2; i++) {
        int id = tid + i * 256, r = id >> 2, c = id & 3;
        aptr[i] = A + (long)(m0 + r) * lda + k0 + c * 8;
        asto[i] = aoff(r, c);
    }
    const float* bp32[4]; uint32_t bs32[4];
#pragma unroll
    for (int i = 0; i < 4; i++) {
        int id = tid + i * 256, k = id >> 5, c = id & 31;
        bp32[i] = B + (long)(k0 + k) * ldb + n0 + c * 4;
        bs32[i] = ABYTES + k * 512 + c * 16;
    }

    const int aRowL = lane & 15, aChL = lane >> 4;

    float acc[4][4][4];
#pragma unroll
    for (int i = 0; i < 4; i++)
#pragma unroll
        for (int j = 0; j < 4; j++)
#pragma unroll
            for (int l = 0; l < 4; l++) acc[i][j][l] = 0.f;

#pragma unroll
    for (int s = 0; s < 3; s++) {
        const uint32_t st = sb + s * STAGE;
        const long ka = (long)s * 32;
        cp16(st + asto[0], aptr[0] + ka);
        cp16(st + asto[1], aptr[1] + ka);
#pragma unroll
        for (int i = 0; i < 4; i++) cp16(st + bs32[i], bp32[i] + ka * ldb);
        CP_COMMIT();
    }

    for (int t = 0; t < kIters; t++) {
        CP_WAIT2();
        __syncthreads();
#pragma unroll
        for (int i = 0; i < 2; i++) {
            int id = tid + i * 256, k = id >> 4, c = id & 15;
            const char* src = smx + (t & 3) * STAGE + ABYTES + k * 512 + c * 32;
            float4 f0 = *(const float4*)(src);
            float4 f1 = *(const float4*)(src + 16);
            uint4 u;
            u.x = pack2(f0.x, f0.y); u.y = pack2(f0.z, f0.w);
            u.z = pack2(f1.x, f1.y); u.w = pack2(f1.z, f1.w);
            *(uint4*)(smx + CONVOFF + (t & 1) * CONVSZ + boff<128>(k, c)) = u;
        }
        if (t + 3 < kIters) {
            const uint32_t st = sb + ((t + 3) & 3) * STAGE;
            const long ka = (long)(t + 3) * 32;
            cp16(st + asto[0], aptr[0] + ka);
            cp16(st + asto[1], aptr[1] + ka);
#pragma unroll
            for (int i = 0; i < 4; i++) cp16(st + bs32[i], bp32[i] + ka * ldb);
        }
        CP_COMMIT();
        __syncthreads();
        const uint32_t sa = sb + (t & 3) * STAGE;
        const uint32_t sbB = sb + CONVOFF + (t & 1) * CONVSZ;
#pragma unroll
        for (int kk = 0; kk < 2; kk++) {
            uint32_t af[4][4], bf[2][4];
#pragma unroll
            for (int mt = 0; mt < 4; mt++)
                ldsm_x4(af[mt], sa + aoff(wm * 64 + mt * 16 + aRowL, kk * 2 + aChL));
#pragma unroll
            for (int ntp = 0; ntp < 2; ntp++)
                ldsm_x4_t(bf[ntp], sbB + boff<128>(kk * 16 + aRowL,
                                                   wn * 4 + ntp * 2 + aChL));
#pragma unroll
            for (int mt = 0; mt < 4; mt++)
#pragma unroll
                for (int ntp = 0; ntp < 2; ntp++) {
                    mma_fp16(acc[mt][ntp * 2 + 0], af[mt], &bf[ntp][0]);
                    mma_fp16(acc[mt][ntp * 2 + 1], af[mt], &bf[ntp][2]);
                }
        }
    }

    float* Cp = C + (long)blockIdx.z * cSplit;
#pragma unroll
    for (int mt = 0; mt < 4; mt++) {
        int r0 = m0 + wm * 64 + mt * 16 + gid;
#pragma unroll
        for (int nt = 0; nt < 4; nt++) {
            int col = n0 + wn * 32 + nt * 8 + tg * 2;
            float2 v0 = make_float2(acc[mt][nt][0], acc[mt][nt][1]);
            float2 v1 = make_float2(acc[mt][nt][2], acc[mt][nt][3]);
            if (bias) {
                float2 bv = *(const float2*)(bias + col);
                v0.x += bv.x; v0.y += bv.y; v1.x += bv.x; v1.y += bv.y;
            }
            if (residh) {
                __half2 q0 = *(const __half2*)(residh + (long)r0 * ldc + col);
                __half2 q1 = *(const __half2*)(residh + (long)(r0 + 8) * ldc + col);
                float2 f0 = __half22float2(q0), f1 = __half22float2(q1);
                v0.x += f0.x; v0.y += f0.y; v1.x += f1.x; v1.y += f1.y;
            }
            *(float2*)(Cp + (long)r0 * ldc + col) = v0;
            *(float2*)(Cp + (long)(r0 + 8) * ldc + col) = v1;
        }
    }
}

// ------------------------------------------------------------------
// Small fp16 GEMM (Wf): BM=128, BN=64, BK=32, 256 thr, fp16 B.
// ------------------------------------------------------------------
__global__ __launch_bounds__(256) void gemm16s(
    const __half* __restrict__ A, int lda,
    const __half* __restrict__ B, int ldb,
    float* __restrict__ C, int ldc,
    int kIters, int kChunk, long cSplit)
{
    constexpr int ABYTES = 128 * 64;
    constexpr int BBYTES = 32 * 128;
    __shared__ char sm[2][ABYTES + BBYTES];

    const int tid = threadIdx.x;
    const int m0 = blockIdx.y * 128;
    const int n0 = blockIdx.x * 64;
    const int k0 = blockIdx.z * kChunk;
    const int warp = tid >> 5, lane = tid & 31;
    const int wm = warp >> 1, wn = warp & 1;
    const int gid = lane >> 2, tg = lane & 3;

    const __half* aptr[2]; int asto[2];
#pragma unroll
    for (int i = 0; i < 2; i++) {
        int id = tid + i * 256, r = id >> 2, c = id & 3;
        aptr[i] = A + (long)(m0 + r) * lda + k0 + c * 8;
        asto[i] = aoff(r, c);
    }
    const __half* bptr; int bsto;
    {
        int k = tid >> 3, c = tid & 7;
        bptr = B + (long)(k0 + k) * ldb + n0 + c * 8;
        bsto = ABYTES + boff<64>(k, c);
    }

    const int aRowL = lane & 15, aChL = lane >> 4;
    uint32_t sbase[2] = { smem_u32(&sm[0][0]), smem_u32(&sm[1][0]) };

    float acc[2][4][4];
#pragma unroll
    for (int i = 0; i < 2; i++)
#pragma unroll
        for (int j = 0; j < 4; j++)
#pragma unroll
            for (int l = 0; l < 4; l++) acc[i][j][l] = 0.f;

    uint4 rau[2], rbu;
#pragma unroll
    for (int i = 0; i < 2; i++) rau[i] = *(const uint4*)(aptr[i]);
    rbu = *(const uint4*)(bptr);
#pragma unroll
    for (int i = 0; i < 2; i++) *(uint4*)&sm[0][asto[i]] = rau[i];
    *(uint4*)&sm[0][bsto] = rbu;
    __syncthreads();

    for (int t = 0; t < kIters; t++) {
        if (t + 1 < kIters) {
            const long ka = (long)(t + 1) * 32;
#pragma unroll
            for (int i = 0; i < 2; i++) rau[i] = *(const uint4*)(aptr[i] + ka);
            rbu = *(const uint4*)(bptr + ka * ldb);
        }
        const uint32_t sa = sbase[t & 1];
        const uint32_t sbB = sbase[t & 1] + ABYTES;
#pragma unroll
        for (int kk = 0; kk < 2; kk++) {
            uint32_t af[2][4], bf[2][4];
#pragma unroll
            for (int mt = 0; mt < 2; mt++)
                ldsm_x4(af[mt], sa + aoff(wm * 32 + mt * 16 + aRowL, kk * 2 + aChL));
#pragma unroll
            for (int ntp = 0; ntp < 2; ntp++)
                ldsm_x4_t(bf[ntp], sbB + boff<64>(kk * 16 + aRowL,
                                                  wn * 4 + ntp * 2 + aChL));
#pragma unroll
            for (int mt = 0; mt < 2; mt++)
#pragma unroll
                for (int ntp = 0; ntp < 2; ntp++) {
                    mma_fp16(acc[mt][ntp * 2 + 0], af[mt], &bf[ntp][0]);
                    mma_fp16(acc[mt][ntp * 2 + 1], af[mt], &bf[ntp][2]);
                }
        }
        if (t + 1 < kIters) {
            char* d = sm[(t + 1) & 1];
#pragma unroll
            for (int i = 0; i < 2; i++) *(uint4*)&d[asto[i]] = rau[i];
            *(uint4*)&d[bsto] = rbu;
            __syncthreads();
        }
    }

    float* Cp = C + (long)blockIdx.z * cSplit;
#pragma unroll
    for (int mt = 0; mt < 2; mt++) {
        int r0 = m0 + wm * 32 + mt * 16 + gid;
#pragma unroll
        for (int nt = 0; nt < 4; nt++) {
            int col = n0 + wn * 32 + nt * 8 + tg * 2;
            *(float2*)(Cp + (long)r0 * ldc + col) =
                make_float2(acc[mt][nt][0], acc[mt][nt][1]);
            *(float2*)(Cp + (long)(r0 + 8) * ldc + col) =
                make_float2(acc[mt][nt][2], acc[mt][nt][3]);
        }
    }
}

// ------------------------------------------------------------------
// MMA attention per (b,h): QKV packed [16384,1536]; fp16 in/out.
// ------------------------------------------------------------------
__global__ __launch_bounds__(128) void attn_mma(
    const __half* __restrict__ QKV, __half* __restrict__ Ctx)
{
    __shared__ __align__(16) char sq[64 * 128], sk[64 * 128], sv[64 * 128];
    const int tid = threadIdx.x;
    const int w = tid >> 5, lane = tid & 31;
    const int gid = lane >> 2, tg = lane & 3;
    const int b = blockIdx.x >> 3, h = blockIdx.x & 7;
    const long base = (long)(b * 64) * 1536 + h * 64;

#pragma unroll
    for (int i = 0; i < 4; i++) {
        int id = tid + i * 128, r = id >> 3, c = id & 7;
        int so = foff(r, c);
        const long go = base + (long)r * 1536 + c * 8;
        *(uint4*)(sq + so) = *(const uint4*)(QKV + go);
        *(uint4*)(sk + so) = *(const uint4*)(QKV + go + 512);
        *(uint4*)(sv + so) = *(const uint4*)(QKV + go + 1024);
    }
    __syncthreads();

    const uint32_t sqb = smem_u32(sq), skb = smem_u32(sk), svb = smem_u32(sv);
    const int rowL = lane & 15, chL = lane >> 4;

    float sacc[8][4];
#pragma unroll
    for (int j = 0; j < 8; j++)
#pragma unroll
        for (int l = 0; l < 4; l++) sacc[j][l] = 0.f;
#pragma unroll
    for (int kk = 0; kk < 4; kk++) {
        uint32_t a[4];
        ldsm_x4(a, sqb + foff(w * 16 + rowL, kk * 2 + chL));
#pragma unroll
        for (int g = 0; g < 4; g++) {
            uint32_t bk[4];
            ldsm_x4(bk, skb + foff(g * 16 + rowL, kk * 2 + chL));
            mma_fp16_2(sacc[g * 2 + 0], a, bk[0], bk[2]);
            mma_fp16_2(sacc[g * 2 + 1], a, bk[1], bk[3]);
        }
    }

    float mx0 = -1e30f, mx1 = -1e30f;
#pragma unroll
    for (int j = 0; j < 8; j++) {
#pragma unroll
        for (int l = 0; l < 4; l++) sacc[j][l] *= 0.125f;
        mx0 = fmaxf(mx0, fmaxf(sacc[j][0], sacc[j][1]));
        mx1 = fmaxf(mx1, fmaxf(sacc[j][2], sacc[j][3]));
    }
#pragma unroll
    for (int o = 1; o < 4; o <<= 1) {
        mx0 = fmaxf(mx0, __shfl_xor_sync(~0u, mx0, o));
        mx1 = fmaxf(mx1, __shfl_xor_sync(~0u, mx1, o));
    }
    float s0 = 0.f, s1 = 0.f;
#pragma unroll
    for (int j = 0; j < 8; j++) {
        sacc[j][0] = __expf(sacc[j][0] - mx0);
        sacc[j][1] = __expf(sacc[j][1] - mx0);
        sacc[j][2] = __expf(sacc[j][2] - mx1);
        sacc[j][3] = __expf(sacc[j][3] - mx1);
        s0 += sacc[j][0] + sacc[j][1];
        s1 += sacc[j][2] + sacc[j][3];
    }
#pragma unroll
    for (int o = 1; o < 4; o <<= 1) {
        s0 += __shfl_xor_sync(~0u, s0, o);
        s1 += __shfl_xor_sync(~0u, s1, o);
    }
    const float r0 = 1.f / s0, r1 = 1.f / s1;

    uint32_t ap[4][4];
#pragma unroll
    for (int kk = 0; kk < 4; kk++) {
        ap[kk][0] = pack2(sacc[kk * 2][0], sacc[kk * 2][1]);
        ap[kk][1] = pack2(sacc[kk * 2][2], sacc[kk * 2][3]);
        ap[kk][2] = pack2(sacc[kk * 2 + 1][0], sacc[kk * 2 + 1][1]);
        ap[kk][3] = pack2(sacc[kk * 2 + 1][2], sacc[kk * 2 + 1][3]);
    }

    float cacc[8][4];
#pragma unroll
    for (int j = 0; j < 8; j++)
#pragma unroll
        for (int l = 0; l < 4; l++) cacc[j][l] = 0.f;
#pragma unroll
    for (int kk = 0; kk < 4; kk++) {
#pragma unroll
        for (int g = 0; g < 4; g++) {
            uint32_t bv[4];
            ldsm_x4_t(bv, svb + foff(kk * 16 + rowL, g * 2 + chL));
            mma_fp16_2(cacc[g * 2 + 0], ap[kk], bv[0], bv[1]);
            mma_fp16_2(cacc[g * 2 + 1], ap[kk], bv[2], bv[3]);
        }
    }

    const long orow0 = (long)(b * 64 + w * 16 + gid) * 512 + h * 64;
    const long orow1 = orow0 + 8 * 512;
#pragma unroll
    for (int nt = 0; nt < 8; nt++) {
        int col = nt * 8 + tg * 2;
        *(__half2*)(Ctx + orow0 + col) = __floats2half2_rn(cacc[nt][0] * r0, cacc[nt][1] * r0);
        *(__half2*)(Ctx + orow1 + col) = __floats2half2_rn(cacc[nt][2] * r1, cacc[nt][3] * r1);
    }
}

// ---------------- prep / post kernels ----------------
__global__ void cvt_f2h(const float* __restrict__ in, __half* __restrict__ out)
{
    int idx = blockIdx.x * 256 + threadIdx.x;
    float4 f = ((const float4*)in)[idx];
    __half2* o = (__half2*)out + idx * 2;
    o[0] = __floats2half2_rn(f.x, f.y);
    o[1] = __floats2half2_rn(f.z, f.w);
}

// convert Wq/Wk/Wv/Wo (each 262144 fp32) in one kernel; grid 1024
__global__ void prep_w(const float* __restrict__ Wq, const float* __restrict__ Wk,
                       const float* __restrict__ Wv, const float* __restrict__ Wo,
                       __half* __restrict__ wqkvh, __half* __restrict__ woh)
{
    int idx = blockIdx.x * 256 + threadIdx.x;   // < 262144 float4s
    int a = idx >> 16, i = idx & 65535;
    const float* src = (a == 0) ? Wq : (a == 1) ? Wk : (a == 2) ? Wv : Wo;
    __half* dst = (a == 0) ? wqkvh : (a == 1) ? wqkvh + 262144
                : (a == 2) ? wqkvh + 524288 : woh;
    float4 f = ((const float4*)src)[i];
    __half2* o = (__half2*)dst + i * 2;
    o[0] = __floats2half2_rn(f.x, f.y);
    o[1] = __floats2half2_rn(f.z, f.w);
}

__global__ void cat_bias_k(const float* bq, const float* bk, const float* bv, float* o)
{
    int i = blockIdx.x * 256 + threadIdx.x;
    o[i] = (i < 512) ? bq[i] : (i < 1024 ? bk[i - 512] : bv[i - 1024]);
}

__global__ void pad_wf_h(const float* __restrict__ Wf, __half* __restrict__ Wfp)
{
    int idx = blockIdx.x * 256 + threadIdx.x;  // < 32768*64
    int k = idx >> 6, j = idx & 63;
    Wfp[idx] = (j < 50) ? __float2half_rn(Wf[k * 50 + j]) : __ushort_as_half(0);
}

__global__ __launch_bounds__(256) void ln512_h(
    const float* __restrict__ in, __half* __restrict__ outh,
    const float* __restrict__ gam, const float* __restrict__ bet)
{
    const int row = blockIdx.x * 8 + (threadIdx.x >> 5);
    const int lane = threadIdx.x & 31;
    const float* p = in + (long)row * 512;
    float v[16], s = 0.f, s2 = 0.f;
#pragma unroll
    for (int i = 0; i < 16; i++) {
        v[i] = p[lane + 32 * i]; s += v[i]; s2 = fmaf(v[i], v[i], s2);
    }
#pragma unroll
    for (int o = 16; o > 0; o >>= 1) {
        s += __shfl_xor_sync(~0u, s, o); s2 += __shfl_xor_sync(~0u, s2, o);
    }
    float mu = s * (1.f / 512.f);
    float rsg = rsqrtf(s2 * (1.f / 512.f) - mu * mu + 1e-5f);
    __half* qh = outh + (long)row * 512;
#pragma unroll
    for (int i = 0; i < 16; i++) {
        int c = lane + 32 * i;
        qh[c] = __float2half_rn((v[i] - mu) * rsg * gam[c] + bet[c]);
    }
}

__global__ __launch_bounds__(1024) void ln32k_h(
    const float* __restrict__ in, __half* __restrict__ out,
    const float* __restrict__ gam, const float* __restrict__ bet)
{
    __shared__ float rs1[32], rs2[32], stat[2];
    const int row = blockIdx.x;
    const float* p = in + (long)row * 32768;
    float s = 0.f, s2 = 0.f;
    for (int i = threadIdx.x; i < 32768; i += 1024) {
        float v = p[i]; s += v; s2 = fmaf(v, v, s2);
    }
#pragma unroll
    for (int o = 16; o > 0; o >>= 1) {
        s += __shfl_xor_sync(~0u, s, o); s2 += __shfl_xor_sync(~0u, s2, o);
    }
    if ((threadIdx.x & 31) == 0) { rs1[threadIdx.x >> 5] = s; rs2[threadIdx.x >> 5] = s2; }
    __syncthreads();
    if (threadIdx.x < 32) {
        s = rs1[threadIdx.x]; s2 = rs2[threadIdx.x];
#pragma unroll
        for (int o = 16; o > 0; o >>= 1) {
            s += __shfl_xor_sync(~0u, s, o); s2 += __shfl_xor_sync(~0u, s2, o);
        }
        if (threadIdx.x == 0) {
            float mu = s * (1.f / 32768.f);
            stat[0] = mu; stat[1] = rsqrtf(s2 * (1.f / 32768.f) - mu * mu + 1e-5f);
        }
    }
    __syncthreads();
    float mu = stat[0], rsg = stat[1];
    __half* q = out + (long)row * 32768;
    for (int i = threadIdx.x; i < 32768; i += 1024)
        q[i] = __float2half_rn((p[i] - mu) * rsg * gam[i] + bet[i]);
}

__global__ void reduce8_relu_h(const float* __restrict__ part,
                               const float* __restrict__ b1, __half* __restrict__ out)
{
    int idx = blockIdx.x * 256 + threadIdx.x;  // < 524288
    float s = 0.f;
#pragma unroll
    for (int z = 0; z < 8; z++) s += part[(long)z * 524288 + idx];
    s += b1[idx & 2047];
    out[idx] = __float2half_rn(fmaxf(s, 0.f));
}

__global__ void reduce_out_k(const float* __restrict__ part,
                             const float* __restrict__ bf, float* __restrict__ out)
{
    int idx = blockIdx.x * 256 + threadIdx.x;
    if (idx >= 12800) return;
    int m = idx / 50, j = idx % 50;
    float s = bf[j];
#pragma unroll
    for (int z = 0; z < 64; z++) s += part[(long)z * 16384 + m * 64 + j];
    out[idx] = s;
}

// ------------------------------------------------------------------
extern "C" void kernel_launch(void* const* d_in, const int* in_sizes, int n_in,
                              void* d_out, int out_size)
{
    const float* inputs = (const float*)d_in[0];
    const float* Wq = (const float*)d_in[1];  const float* bq = (const float*)d_in[2];
    const float* Wk = (const float*)d_in[3];  const float* bk = (const float*)d_in[4];
    const float* Wv = (const float*)d_in[5];  const float* bv = (const float*)d_in[6];
    const float* Wo = (const float*)d_in[7];  const float* bo = (const float*)d_in[8];
    const float* ln1g = (const float*)d_in[9];  const float* ln1b = (const float*)d_in[10];
    const float* W1 = (const float*)d_in[11]; const float* b1 = (const float*)d_in[12];
    const float* W2 = (const float*)d_in[13]; const float* b2 = (const float*)d_in[14];
    const float* ln2g = (const float*)d_in[15]; const float* ln2b = (const float*)d_in[16];
    const float* Wf = (const float*)d_in[17]; const float* bf = (const float*)d_in[18];
    float* out = (float*)d_out;

    __half *inh, *qkvh, *ctxh, *xh, *hh, *yh, *wqkvh, *woh, *wfph;
    float *bqkv, *res1, *p4, *v2, *p6;
    cudaGetSymbolAddress((void**)&inh, g_inh);
    cudaGetSymbolAddress((void**)&qkvh, g_qkvh);
    cudaGetSymbolAddress((void**)&ctxh, g_ctxh);
    cudaGetSymbolAddress((void**)&xh, g_xh);
    cudaGetSymbolAddress((void**)&hh, g_hh);
    cudaGetSymbolAddress((void**)&yh, g_yh);
    cudaGetSymbolAddress((void**)&wqkvh, g_wqkvh);
    cudaGetSymbolAddress((void**)&woh, g_woh);
    cudaGetSymbolAddress((void**)&wfph, g_wfph);
    cudaGetSymbolAddress((void**)&bqkv, g_bqkv);
    cudaGetSymbolAddress((void**)&res1, g_res1);
    cudaGetSymbolAddress((void**)&p4, g_p4);
    cudaGetSymbolAddress((void**)&v2, g_v2);
    cudaGetSymbolAddress((void**)&p6, g_p6);

    constexpr int SMF = 3 * 32768;              // 98304 (fp16-B BK=64)
    constexpr int SMW = 4 * 24576 + 2 * 8192;   // 114688 (fp32-B)
    cudaFuncSetAttribute((const void*)gemmf64<true>,
                         cudaFuncAttributeMaxDynamicSharedMemorySize, SMF);
    cudaFuncSetAttribute((const void*)gemmf64<false>,
                         cudaFuncAttributeMaxDynamicSharedMemorySize, SMF);
    cudaFuncSetAttribute((const void*)gemmw,
                         cudaFuncAttributeMaxDynamicSharedMemorySize, SMW);

    // prep
    pad_wf_h<<<8192, 256>>>(Wf, wfph);
    cvt_f2h<<<8192, 256>>>(inputs, inh);
    prep_w<<<1024, 256>>>(Wq, Wk, Wv, Wo, wqkvh, woh);
    cat_bias_k<<<6, 256>>>(bq, bk, bv, bqkv);

    // fused QKV -> qkvh [16384, 1536]
    gemmf64<true><<<dim3(12, 128), 256, SMF>>>(
        inh, 512, wqkvh, 0, 32768, qkvh, 1536, 8, bqkv, nullptr);

    // MMA attention
    attn_mma<<<2048, 128>>>(qkvh, ctxh);

    // output projection + bias + residual(inputs) -> fp32 res1
    gemmf64<false><<<dim3(4, 128), 256, SMF>>>(
        ctxh, 512, woh, 512, 0, res1, 512, 8, bo, inputs);

    // LN1 -> xh (fp16 only)
    ln512_h<<<2048, 256>>>(res1, xh, ln1g, ln1b);

    // h = relu(x @ W1 + b1): split-K 8 (one clean 2-CTA/SM wave)
    gemmw<<<dim3(16, 2, 8), 256, SMW>>>(
        xh, 32768, W1, 2048, p4, 2048, 128, 4096, 524288, nullptr, nullptr);
    reduce8_relu_h<<<2048, 256>>>(p4, b1, hh);

    // v2 = h @ W2 + b2 + xh(fp16 residual) -> fp32
    gemmw<<<dim3(256, 2, 1), 256, SMW>>>(
        hh, 2048, W2, 32768, v2, 32768, 64, 0, 0, b2, xh);

    // LN2 -> yh fp16
    ln32k_h<<<256, 1024>>>(v2, yh, ln2g, ln2b);

    // logits: y @ wfph split-K 64
    gemm16s<<<dim3(1, 2, 64), 256>>>(yh, 32768, wfph, 64, p6, 64, 16, 512, 16384);
    reduce_out_k<<<50, 256>>>(p6, bf, out);
}

// round 17
// speedup vs baseline: 1.1727x; 1.0371x over previous
#include <cuda_runtime.h>
#include <cuda_fp16.h>
#include <cstdint>

// B=256, S=64, D=512, H=8, DK=DV=64, DFF=2048, IN=32768, OUT=50

// ---------------- device scratch (static, no allocation) ----------------
__device__ __half g_inh  [16384L*512];
__device__ __half g_qkvh [16384L*1536];
__device__ __half g_ctxh [16384L*512];
__device__ __half g_res1h[16384L*512];
__device__ __half g_xh   [256L*32768];
__device__ __half g_hh   [256L*2048];
__device__ __half g_v2h  [256L*32768];
__device__ __half g_yh   [256L*32768];
__device__ __half g_wqkvh[24L*512*64];
__device__ __half g_woh  [512L*512];
__device__ __half g_wfph [32768L*64];
__device__ float  g_bqkv [1536];
__device__ float  g_p4   [8L*256*2048];
__device__ float  g_p6   [64L*256*64];

// ---------------- helpers ----------------
__device__ __forceinline__ uint32_t pack2(float a, float b) {
    __half2 h = __floats2half2_rn(a, b);
    return *reinterpret_cast<uint32_t*>(&h);
}
__device__ __forceinline__ int aoff(int r, int c) {   // 64B rows, paired atoms
    return ((r >> 1) << 7) + (((((r & 1) << 2) + c) ^ ((r >> 1) & 7)) << 4);
}
template<int BN>
__device__ __forceinline__ int boff(int k, int c) {   // 2*BN B rows
    return k * (2 * BN) + ((((c & ~7) | ((c ^ (k & 7)) & 7))) << 4);
}
__device__ __forceinline__ int foff(int r, int c) {   // 128B rows
    return (r << 7) + (((c ^ (r & 7)) & 7) << 4);
}
__device__ __forceinline__ void ldsm_x4(uint32_t* r, uint32_t addr) {
    asm volatile("ldmatrix.sync.aligned.m8n8.x4.shared.b16 {%0,%1,%2,%3}, [%4];"
                 : "=r"(r[0]), "=r"(r[1]), "=r"(r[2]), "=r"(r[3]) : "r"(addr));
}
__device__ __forceinline__ void ldsm_x4_t(uint32_t* r, uint32_t addr) {
    asm volatile("ldmatrix.sync.aligned.m8n8.x4.trans.shared.b16 {%0,%1,%2,%3}, [%4];"
                 : "=r"(r[0]), "=r"(r[1]), "=r"(r[2]), "=r"(r[3]) : "r"(addr));
}
__device__ __forceinline__ void mma_fp16(float* d, const uint32_t* a, const uint32_t* b) {
    asm volatile(
        "mma.sync.aligned.m16n8k16.row.col.f32.f16.f16.f32 "
        "{%0,%1,%2,%3},{%4,%5,%6,%7},{%8,%9},{%0,%1,%2,%3};"
        : "+f"(d[0]), "+f"(d[1]), "+f"(d[2]), "+f"(d[3])
        : "r"(a[0]), "r"(a[1]), "r"(a[2]), "r"(a[3]), "r"(b[0]), "r"(b[1]));
}
__device__ __forceinline__ void mma_fp16_2(float* d, const uint32_t* a, uint32_t b0, uint32_t b1) {
    asm volatile(
        "mma.sync.aligned.m16n8k16.row.col.f32.f16.f16.f32 "
        "{%0,%1,%2,%3},{%4,%5,%6,%7},{%8,%9},{%0,%1,%2,%3};"
        : "+f"(d[0]), "+f"(d[1]), "+f"(d[2]), "+f"(d[3])
        : "r"(a[0]), "r"(a[1]), "r"(a[2]), "r"(a[3]), "r"(b0), "r"(b1));
}
__device__ __forceinline__ uint32_t smem_u32(const void* p) {
    uint32_t a;
    asm("{ .reg .u64 t; cvta.to.shared.u64 t, %1; cvt.u32.u64 %0, t; }" : "=r"(a) : "l"(p));
    return a;
}
__device__ __forceinline__ void cp16(uint32_t saddr, const void* g) {
    asm volatile("cp.async.cg.shared.global [%0], [%1], 16;" :: "r"(saddr), "l"(g));
}
#define CP_COMMIT() asm volatile("cp.async.commit_group;" ::: "memory")
#define CP_WAIT1()  asm volatile("cp.async.wait_group 1;" ::: "memory")
#define CP_WAIT2()  asm volatile("cp.async.wait_group 2;" ::: "memory")

// ------------------------------------------------------------------
// fp16-B GEMM, BK=64, 3-stage cp.async, BM=128 BN=128, 256 thr (2x4),
// 2 CTAs/SM. OH: fp16 out (+bias, +fp32 resid), else fp32 (+bias/resid).
// ------------------------------------------------------------------
template<bool OH>
__global__ __launch_bounds__(256, 2) void gemmf64(
    const __half* __restrict__ A, int lda,
    const __half* __restrict__ B, int ldb, int headStride,
    void* __restrict__ Cv, int ldc, int kIters,
    const float* __restrict__ bias,
    const float* __restrict__ resid)
{
    constexpr int ABYTES = 128 * 128;
    constexpr int STAGE  = ABYTES + 64 * 256;  // 32768
    extern __shared__ char smx[];
    const uint32_t sb = smem_u32(smx);

    const int tid = threadIdx.x;
    const int m0 = blockIdx.y * 128;
    const int n0 = blockIdx.x * 128;
    const int warp = tid >> 5, lane = tid & 31;
    const int wm = warp >> 2, wn = warp & 3;
    const int gid = lane >> 2, tg = lane & 3;

    const __half* aptr[4]; uint32_t asto[4];
#pragma unroll
    for (int i = 0; i < 4; i++) {
        int id = tid + i * 256, r = id >> 3, c = id & 7;
        aptr[i] = A + (long)(m0 + r) * lda + c * 8;
        asto[i] = foff(r, c);
    }
    const int rowStr = headStride ? 64 : ldb;
    const __half* bptr[4]; uint32_t bsto[4];
#pragma unroll
    for (int i = 0; i < 4; i++) {
        int id = tid + i * 256, k = id >> 4, c = id & 15;
        int col = n0 + c * 8;
        const __half* bb = headStride ? (B + (long)(col >> 6) * headStride + (col & 63))
                                      : (B + col);
        bptr[i] = bb + (long)k * rowStr;
        bsto[i] = ABYTES + boff<128>(k, c);
    }

    const int rowL = lane & 15, chL = lane >> 4;

    float acc[4][4][4];
#pragma unroll
    for (int i = 0; i < 4; i++)
#pragma unroll
        for (int j = 0; j < 4; j++)
#pragma unroll
            for (int l = 0; l < 4; l++) acc[i][j][l] = 0.f;

#pragma unroll
    for (int s = 0; s < 2; s++) {
        const uint32_t st = sb + s * STAGE;
        const long ka = (long)s * 64;
#pragma unroll
        for (int i = 0; i < 4; i++) cp16(st + asto[i], aptr[i] + ka);
#pragma unroll
        for (int i = 0; i < 4; i++) cp16(st + bsto[i], bptr[i] + ka * rowStr);
        CP_COMMIT();
    }

    for (int t = 0; t < kIters; t++) {
        CP_WAIT1();
        __syncthreads();
        if (t + 2 < kIters) {
            const uint32_t st = sb + ((t + 2) % 3) * STAGE;
            const long ka = (long)(t + 2) * 64;
#pragma unroll
            for (int i = 0; i < 4; i++) cp16(st + asto[i], aptr[i] + ka);
#pragma unroll
            for (int i = 0; i < 4; i++) cp16(st + bsto[i], bptr[i] + ka * rowStr);
        }
        CP_COMMIT();
        const uint32_t sa = sb + (t % 3) * STAGE;
        const uint32_t sbB = sa + ABYTES;
#pragma unroll
        for (int kk = 0; kk < 4; kk++) {
            uint32_t af[4][4], bf[2][4];
#pragma unroll
            for (int mt = 0; mt < 4; mt++)
                ldsm_x4(af[mt], sa + foff(wm * 64 + mt * 16 + rowL, kk * 2 + chL));
#pragma unroll
            for (int ntp = 0; ntp < 2; ntp++)
                ldsm_x4_t(bf[ntp], sbB + boff<128>(kk * 16 + rowL,
                                                   wn * 4 + ntp * 2 + chL));
#pragma unroll
            for (int mt = 0; mt < 4; mt++)
#pragma unroll
                for (int ntp = 0; ntp < 2; ntp++) {
                    mma_fp16(acc[mt][ntp * 2 + 0], af[mt], &bf[ntp][0]);
                    mma_fp16(acc[mt][ntp * 2 + 1], af[mt], &bf[ntp][2]);
                }
        }
    }

#pragma unroll
    for (int mt = 0; mt < 4; mt++) {
        int r0 = m0 + wm * 64 + mt * 16 + gid;
#pragma unroll
        for (int nt = 0; nt < 4; nt++) {
            int col = n0 + wn * 32 + nt * 8 + tg * 2;
            float2 v0 = make_float2(acc[mt][nt][0], acc[mt][nt][1]);
            float2 v1 = make_float2(acc[mt][nt][2], acc[mt][nt][3]);
            if (bias) {
                float2 bv = *(const float2*)(bias + col);
                v0.x += bv.x; v0.y += bv.y; v1.x += bv.x; v1.y += bv.y;
            }
            if (resid) {
                float2 q0 = *(const float2*)(resid + (long)r0 * ldc + col);
                float2 q1 = *(const float2*)(resid + (long)(r0 + 8) * ldc + col);
                v0.x += q0.x; v0.y += q0.y; v1.x += q1.x; v1.y += q1.y;
            }
            if (OH) {
                __half* Ch = (__half*)Cv;
                *(__half2*)(Ch + (long)r0 * ldc + col) = __floats2half2_rn(v0.x, v0.y);
                *(__half2*)(Ch + (long)(r0 + 8) * ldc + col) = __floats2half2_rn(v1.x, v1.y);
            } else {
                float* Cp = (float*)Cv;
                *(float2*)(Cp + (long)r0 * ldc + col) = v0;
                *(float2*)(Cp + (long)(r0 + 8) * ldc + col) = v1;
            }
        }
    }
}

// ------------------------------------------------------------------
// fp32-B GEMM (W1/W2): BM=128 BN=128 BK=32, 4-stage cp.async, smem
// convert, 256 thr, 2 CTAs/SM. OHALF: fp16 out (+bias+residh).
// ------------------------------------------------------------------
template<bool OHALF>
__global__ __launch_bounds__(256, 2) void gemmw(
    const __half* __restrict__ A, int lda,
    const float* __restrict__ B, int ldb,
    void* __restrict__ Cv, int ldc,
    int kIters, int kChunk, long cSplit,
    const float* __restrict__ bias,
    const __half* __restrict__ residh)
{
    constexpr int ABYTES = 128 * 64;
    constexpr int STAGE  = ABYTES + 16384;
    constexpr int CONVOFF = 4 * STAGE;
    constexpr int CONVSZ  = 8192;
    extern __shared__ char smx[];
    const uint32_t sb = smem_u32(smx);

    const int tid = threadIdx.x;
    const int m0 = blockIdx.y * 128;
    const int n0 = blockIdx.x * 128;
    const int k0 = blockIdx.z * kChunk;
    const int warp = tid >> 5, lane = tid & 31;
    const int wm = warp >> 2, wn = warp & 3;
    const int gid = lane >> 2, tg = lane & 3;

    const __half* aptr[2]; uint32_t asto[2];
#pragma unroll
    for (int i = 0; i < 2; i++) {
        int id = tid + i * 256, r = id >> 2, c = id & 3;
        aptr[i] = A + (long)(m0 + r) * lda + k0 + c * 8;
        asto[i] = aoff(r, c);
    }
    const float* bp32[4]; uint32_t bs32[4];
#pragma unroll
    for (int i = 0; i < 4; i++) {
        int id = tid + i * 256, k = id >> 5, c = id & 31;
        bp32[i] = B + (long)(k0 + k) * ldb + n0 + c * 4;
        bs32[i] = ABYTES + k * 512 + c * 16;
    }

    const int aRowL = lane & 15, aChL = lane >> 4;

    float acc[4][4][4];
#pragma unroll
    for (int i = 0; i < 4; i++)
#pragma unroll
        for (int j = 0; j < 4; j++)
#pragma unroll
            for (int l = 0; l < 4; l++) acc[i][j][l] = 0.f;

#pragma unroll
    for (int s = 0; s < 3; s++) {
        const uint32_t st = sb + s * STAGE;
        const long ka = (long)s * 32;
        cp16(st + asto[0], aptr[0] + ka);
        cp16(st + asto[1], aptr[1] + ka);
#pragma unroll
        for (int i = 0; i < 4; i++) cp16(st + bs32[i], bp32[i] + ka * ldb);
        CP_COMMIT();
    }

    for (int t = 0; t < kIters; t++) {
        CP_WAIT2();
        __syncthreads();
#pragma unroll
        for (int i = 0; i < 2; i++) {
            int id = tid + i * 256, k = id >> 4, c = id & 15;
            const char* src = smx + (t & 3) * STAGE + ABYTES + k * 512 + c * 32;
            float4 f0 = *(const float4*)(src);
            float4 f1 = *(const float4*)(src + 16);
            uint4 u;
            u.x = pack2(f0.x, f0.y); u.y = pack2(f0.z, f0.w);
            u.z = pack2(f1.x, f1.y); u.w = pack2(f1.z, f1.w);
            *(uint4*)(smx + CONVOFF + (t & 1) * CONVSZ + boff<128>(k, c)) = u;
        }
        if (t + 3 < kIters) {
            const uint32_t st = sb + ((t + 3) & 3) * STAGE;
            const long ka = (long)(t + 3) * 32;
            cp16(st + asto[0], aptr[0] + ka);
            cp16(st + asto[1], aptr[1] + ka);
#pragma unroll
            for (int i = 0; i < 4; i++) cp16(st + bs32[i], bp32[i] + ka * ldb);
        }
        CP_COMMIT();
        __syncthreads();
        const uint32_t sa = sb + (t & 3) * STAGE;
        const uint32_t sbB = sb + CONVOFF + (t & 1) * CONVSZ;
#pragma unroll
        for (int kk = 0; kk < 2; kk++) {
            uint32_t af[4][4], bf[2][4];
#pragma unroll
            for (int mt = 0; mt < 4; mt++)
                ldsm_x4(af[mt], sa + aoff(wm * 64 + mt * 16 + aRowL, kk * 2 + aChL));
#pragma unroll
            for (int ntp = 0; ntp < 2; ntp++)
                ldsm_x4_t(bf[ntp], sbB + boff<128>(kk * 16 + aRowL,
                                                   wn * 4 + ntp * 2 + aChL));
#pragma unroll
            for (int mt = 0; mt < 4; mt++)
#pragma unroll
                for (int ntp = 0; ntp < 2; ntp++) {
                    mma_fp16(acc[mt][ntp * 2 + 0], af[mt], &bf[ntp][0]);
                    mma_fp16(acc[mt][ntp * 2 + 1], af[mt], &bf[ntp][2]);
                }
        }
    }

#pragma unroll
    for (int mt = 0; mt < 4; mt++) {
        int r0 = m0 + wm * 64 + mt * 16 + gid;
#pragma unroll
        for (int nt = 0; nt < 4; nt++) {
            int col = n0 + wn * 32 + nt * 8 + tg * 2;
            float2 v0 = make_float2(acc[mt][nt][0], acc[mt][nt][1]);
            float2 v1 = make_float2(acc[mt][nt][2], acc[mt][nt][3]);
            if (bias) {
                float2 bv = *(const float2*)(bias + col);
                v0.x += bv.x; v0.y += bv.y; v1.x += bv.x; v1.y += bv.y;
            }
            if (residh) {
                __half2 q0 = *(const __half2*)(residh + (long)r0 * ldc + col);
                __half2 q1 = *(const __half2*)(residh + (long)(r0 + 8) * ldc + col);
                float2 f0 = __half22float2(q0), f1 = __half22float2(q1);
                v0.x += f0.x; v0.y += f0.y; v1.x += f1.x; v1.y += f1.y;
            }
            if (OHALF) {
                __half* Ch = (__half*)Cv;
                *(__half2*)(Ch + (long)r0 * ldc + col) = __floats2half2_rn(v0.x, v0.y);
                *(__half2*)(Ch + (long)(r0 + 8) * ldc + col) = __floats2half2_rn(v1.x, v1.y);
            } else {
                float* Cp = (float*)Cv + (long)blockIdx.z * cSplit;
                *(float2*)(Cp + (long)r0 * ldc + col) = v0;
                *(float2*)(Cp + (long)(r0 + 8) * ldc + col) = v1;
            }
        }
    }
}

// ------------------------------------------------------------------
// Wf GEMM: BM=128, BN=64, BK=32, 4-stage cp.async, fp16 B, 256 thr.
// ------------------------------------------------------------------
__global__ __launch_bounds__(256, 2) void gemm16p(
    const __half* __restrict__ A, int lda,
    const __half* __restrict__ B, int ldb,
    float* __restrict__ C, int ldc,
    int kIters, int kChunk, long cSplit)
{
    constexpr int ABYTES = 128 * 64;    // 8192
    constexpr int STAGE  = ABYTES + 32 * 128;  // +4096 = 12288
    extern __shared__ char smx[];
    const uint32_t sb = smem_u32(smx);

    const int tid = threadIdx.x;
    const int m0 = blockIdx.y * 128;
    const int n0 = blockIdx.x * 64;
    const int k0 = blockIdx.z * kChunk;
    const int warp = tid >> 5, lane = tid & 31;
    const int wm = warp >> 1, wn = warp & 1;
    const int gid = lane >> 2, tg = lane & 3;

    const __half* aptr[2]; uint32_t asto[2];
#pragma unroll
    for (int i = 0; i < 2; i++) {
        int id = tid + i * 256, r = id >> 2, c = id & 3;
        aptr[i] = A + (long)(m0 + r) * lda + k0 + c * 8;
        asto[i] = aoff(r, c);
    }
    const __half* bptr; uint32_t bsto;
    {
        int k = tid >> 3, c = tid & 7;
        bptr = B + (long)(k0 + k) * ldb + n0 + c * 8;
        bsto = ABYTES + boff<64>(k, c);
    }

    const int aRowL = lane & 15, aChL = lane >> 4;

    float acc[2][4][4];
#pragma unroll
    for (int i = 0; i < 2; i++)
#pragma unroll
        for (int j = 0; j < 4; j++)
#pragma unroll
            for (int l = 0; l < 4; l++) acc[i][j][l] = 0.f;

#pragma unroll
    for (int s = 0; s < 3; s++) {
        const uint32_t st = sb + s * STAGE;
        const long ka = (long)s * 32;
        cp16(st + asto[0], aptr[0] + ka);
        cp16(st + asto[1], aptr[1] + ka);
        cp16(st + bsto, bptr + ka * ldb);
        CP_COMMIT();
    }

    for (int t = 0; t < kIters; t++) {
        CP_WAIT2();
        __syncthreads();
        if (t + 3 < kIters) {
            const uint32_t st = sb + ((t + 3) & 3) * STAGE;
            const long ka = (long)(t + 3) * 32;
            cp16(st + asto[0], aptr[0] + ka);
            cp16(st + asto[1], aptr[1] + ka);
            cp16(st + bsto, bptr + ka * ldb);
        }
        CP_COMMIT();
        const uint32_t sa = sb + (t & 3) * STAGE;
        const uint32_t sbB = sa + ABYTES;
#pragma unroll
        for (int kk = 0; kk < 2; kk++) {
            uint32_t af[2][4], bf[2][4];
#pragma unroll
            for (int mt = 0; mt < 2; mt++)
                ldsm_x4(af[mt], sa + aoff(wm * 32 + mt * 16 + aRowL, kk * 2 + aChL));
#pragma unroll
            for (int ntp = 0; ntp < 2; ntp++)
                ldsm_x4_t(bf[ntp], sbB + boff<64>(kk * 16 + aRowL,
                                                  wn * 4 + ntp * 2 + aChL));
#pragma unroll
            for (int mt = 0; mt < 2; mt++)
#pragma unroll
                for (int ntp = 0; ntp < 2; ntp++) {
                    mma_fp16(acc[mt][ntp * 2 + 0], af[mt], &bf[ntp][0]);
                    mma_fp16(acc[mt][ntp * 2 + 1], af[mt], &bf[ntp][2]);
                }
        }
    }

    float* Cp = C + (long)blockIdx.z * cSplit;
#pragma unroll
    for (int mt = 0; mt < 2; mt++) {
        int r0 = m0 + wm * 32 + mt * 16 + gid;
#pragma unroll
        for (int nt = 0; nt < 4; nt++) {
            int col = n0 + wn * 32 + nt * 8 + tg * 2;
            *(float2*)(Cp + (long)r0 * ldc + col) =
                make_float2(acc[mt][nt][0], acc[mt][nt][1]);
            *(float2*)(Cp + (long)(r0 + 8) * ldc + col) =
                make_float2(acc[mt][nt][2], acc[mt][nt][3]);
        }
    }
}

// ------------------------------------------------------------------
// MMA attention per (b,h): QKV packed [16384,1536]; fp16 in/out.
// ------------------------------------------------------------------
__global__ __launch_bounds__(128) void attn_mma(
    const __half* __restrict__ QKV, __half* __restrict__ Ctx)
{
    __shared__ __align__(16) char sq[64 * 128], sk[64 * 128], sv[64 * 128];
    const int tid = threadIdx.x;
    const int w = tid >> 5, lane = tid & 31;
    const int gid = lane >> 2, tg = lane & 3;
    const int b = blockIdx.x >> 3, h = blockIdx.x & 7;
    const long base = (long)(b * 64) * 1536 + h * 64;

#pragma unroll
    for (int i = 0; i < 4; i++) {
        int id = tid + i * 128, r = id >> 3, c = id & 7;
        int so = foff(r, c);
        const long go = base + (long)r * 1536 + c * 8;
        *(uint4*)(sq + so) = *(const uint4*)(QKV + go);
        *(uint4*)(sk + so) = *(const uint4*)(QKV + go + 512);
        *(uint4*)(sv + so) = *(const uint4*)(QKV + go + 1024);
    }
    __syncthreads();

    const uint32_t sqb = smem_u32(sq), skb = smem_u32(sk), svb = smem_u32(sv);
    const int rowL = lane & 15, chL = lane >> 4;

    float sacc[8][4];
#pragma unroll
    for (int j = 0; j < 8; j++)
#pragma unroll
        for (int l = 0; l < 4; l++) sacc[j][l] = 0.f;
#pragma unroll
    for (int kk = 0; kk < 4; kk++) {
        uint32_t a[4];
        ldsm_x4(a, sqb + foff(w * 16 + rowL, kk * 2 + chL));
#pragma unroll
        for (int g = 0; g < 4; g++) {
            uint32_t bk[4];
            ldsm_x4(bk, skb + foff(g * 16 + rowL, kk * 2 + chL));
            mma_fp16_2(sacc[g * 2 + 0], a, bk[0], bk[2]);
            mma_fp16_2(sacc[g * 2 + 1], a, bk[1], bk[3]);
        }
    }

    float mx0 = -1e30f, mx1 = -1e30f;
#pragma unroll
    for (int j = 0; j < 8; j++) {
#pragma unroll
        for (int l = 0; l < 4; l++) sacc[j][l] *= 0.125f;
        mx0 = fmaxf(mx0, fmaxf(sacc[j][0], sacc[j][1]));
        mx1 = fmaxf(mx1, fmaxf(sacc[j][2], sacc[j][3]));
    }
#pragma unroll
    for (int o = 1; o < 4; o <<= 1) {
        mx0 = fmaxf(mx0, __shfl_xor_sync(~0u, mx0, o));
        mx1 = fmaxf(mx1, __shfl_xor_sync(~0u, mx1, o));
    }
    float s0 = 0.f, s1 = 0.f;
#pragma unroll
    for (int j = 0; j < 8; j++) {
        sacc[j][0] = __expf(sacc[j][0] - mx0);
        sacc[j][1] = __expf(sacc[j][1] - mx0);
        sacc[j][2] = __expf(sacc[j][2] - mx1);
        sacc[j][3] = __expf(sacc[j][3] - mx1);
        s0 += sacc[j][0] + sacc[j][1];
        s1 += sacc[j][2] + sacc[j][3];
    }
#pragma unroll
    for (int o = 1; o < 4; o <<= 1) {
        s0 += __shfl_xor_sync(~0u, s0, o);
        s1 += __shfl_xor_sync(~0u, s1, o);
    }
    const float r0 = 1.f / s0, r1 = 1.f / s1;

    uint32_t ap[4][4];
#pragma unroll
    for (int kk = 0; kk < 4; kk++) {
        ap[kk][0] = pack2(sacc[kk * 2][0], sacc[kk * 2][1]);
        ap[kk][1] = pack2(sacc[kk * 2][2], sacc[kk * 2][3]);
        ap[kk][2] = pack2(sacc[kk * 2 + 1][0], sacc[kk * 2 + 1][1]);
        ap[kk][3] = pack2(sacc[kk * 2 + 1][2], sacc[kk * 2 + 1][3]);
    }

    float cacc[8][4];
#pragma unroll
    for (int j = 0; j < 8; j++)
#pragma unroll
        for (int l = 0; l < 4; l++) cacc[j][l] = 0.f;
#pragma unroll
    for (int kk = 0; kk < 4; kk++) {
#pragma unroll
        for (int g = 0; g < 4; g++) {
            uint32_t bv[4];
            ldsm_x4_t(bv, svb + foff(kk * 16 + rowL, g * 2 + chL));
            mma_fp16_2(cacc[g * 2 + 0], ap[kk], bv[0], bv[1]);
            mma_fp16_2(cacc[g * 2 + 1], ap[kk], bv[2], bv[3]);
        }
    }

    const long orow0 = (long)(b * 64 + w * 16 + gid) * 512 + h * 64;
    const long orow1 = orow0 + 8 * 512;
#pragma unroll
    for (int nt = 0; nt < 8; nt++) {
        int col = nt * 8 + tg * 2;
        *(__half2*)(Ctx + orow0 + col) = __floats2half2_rn(cacc[nt][0] * r0, cacc[nt][1] * r0);
        *(__half2*)(Ctx + orow1 + col) = __floats2half2_rn(cacc[nt][2] * r1, cacc[nt][3] * r1);
    }
}

// ---------------- merged prep kernel (block-range dispatch) ----------------
__global__ void prep_all(
    const float* __restrict__ Wf, __half* __restrict__ wfph,
    const float* __restrict__ inputs, __half* __restrict__ inh,
    const float* __restrict__ Wq, const float* __restrict__ Wk,
    const float* __restrict__ Wv, const float* __restrict__ Wo,
    __half* __restrict__ wqkvh, __half* __restrict__ woh,
    const float* __restrict__ bq, const float* __restrict__ bk,
    const float* __restrict__ bv, float* __restrict__ bqkv)
{
    const int bid = blockIdx.x;
    if (bid < 8192) {                       // pad Wf -> fp16 [32768,64]
        int idx = bid * 256 + threadIdx.x;
        int k = idx >> 6, j = idx & 63;
        wfph[idx] = (j < 50) ? __float2half_rn(Wf[k * 50 + j]) : __ushort_as_half(0);
    } else if (bid < 16384) {               // inputs -> fp16 (float4 grain)
        int idx = (bid - 8192) * 256 + threadIdx.x;
        float4 f = ((const float4*)inputs)[idx];
        __half2* o = (__half2*)inh + idx * 2;
        o[0] = __floats2half2_rn(f.x, f.y);
        o[1] = __floats2half2_rn(f.z, f.w);
    } else if (bid < 17408) {               // Wq/Wk/Wv/Wo -> fp16
        int idx = (bid - 16384) * 256 + threadIdx.x;
        int a = idx >> 16, i = idx & 65535;
        const float* src = (a == 0) ? Wq : (a == 1) ? Wk : (a == 2) ? Wv : Wo;
        __half* dst = (a == 0) ? wqkvh : (a == 1) ? wqkvh + 262144
                    : (a == 2) ? wqkvh + 524288 : woh;
        float4 f = ((const float4*)src)[i];
        __half2* o = (__half2*)dst + i * 2;
        o[0] = __floats2half2_rn(f.x, f.y);
        o[1] = __floats2half2_rn(f.z, f.w);
    } else {                                // bias concat
        int i = (bid - 17408) * 256 + threadIdx.x;
        if (i < 1536)
            bqkv[i] = (i < 512) ? bq[i] : (i < 1024 ? bk[i - 512] : bv[i - 1024]);
    }
}

// ---------------- LayerNorms (fp16 in, fp16 out) ----------------
__global__ __launch_bounds__(256) void ln512_hh(
    const __half* __restrict__ in, __half* __restrict__ outh,
    const float* __restrict__ gam, const float* __restrict__ bet)
{
    const int row = blockIdx.x * 8 + (threadIdx.x >> 5);
    const int lane = threadIdx.x & 31;
    const __half* p = in + (long)row * 512;
    float v[16], s = 0.f, s2 = 0.f;
#pragma unroll
    for (int i = 0; i < 16; i++) {
        v[i] = __half2float(p[lane + 32 * i]);
        s += v[i]; s2 = fmaf(v[i], v[i], s2);
    }
#pragma unroll
    for (int o = 16; o > 0; o >>= 1) {
        s += __shfl_xor_sync(~0u, s, o); s2 += __shfl_xor_sync(~0u, s2, o);
    }
    float mu = s * (1.f / 512.f);
    float rsg = rsqrtf(s2 * (1.f / 512.f) - mu * mu + 1e-5f);
    __half* qh = outh + (long)row * 512;
#pragma unroll
    for (int i = 0; i < 16; i++) {
        int c = lane + 32 * i;
        qh[c] = __float2half_rn((v[i] - mu) * rsg * gam[c] + bet[c]);
    }
}

__global__ __launch_bounds__(1024) void ln32k_hh(
    const __half* __restrict__ in, __half* __restrict__ out,
    const float* __restrict__ gam, const float* __restrict__ bet)
{
    __shared__ float rs1[32], rs2[32], stat[2];
    const int row = blockIdx.x;
    const __half* p = in + (long)row * 32768;
    float s = 0.f, s2 = 0.f;
    for (int i = threadIdx.x; i < 32768; i += 1024) {
        float v = __half2float(p[i]);
        s += v; s2 = fmaf(v, v, s2);
    }
#pragma unroll
    for (int o = 16; o > 0; o >>= 1) {
        s += __shfl_xor_sync(~0u, s, o); s2 += __shfl_xor_sync(~0u, s2, o);
    }
    if ((threadIdx.x & 31) == 0) { rs1[threadIdx.x >> 5] = s; rs2[threadIdx.x >> 5] = s2; }
    __syncthreads();
    if (threadIdx.x < 32) {
        s = rs1[threadIdx.x]; s2 = rs2[threadIdx.x];
#pragma unroll
        for (int o = 16; o > 0; o >>= 1) {
            s += __shfl_xor_sync(~0u, s, o); s2 += __shfl_xor_sync(~0u, s2, o);
        }
        if (threadIdx.x == 0) {
            float mu = s * (1.f / 32768.f);
            stat[0] = mu; stat[1] = rsqrtf(s2 * (1.f / 32768.f) - mu * mu + 1e-5f);
        }
    }
    __syncthreads();
    float mu = stat[0], rsg = stat[1];
    __half* q = out + (long)row * 32768;
    for (int i = threadIdx.x; i < 32768; i += 1024)
        q[i] = __float2half_rn((__half2float(p[i]) - mu) * rsg * gam[i] + bet[i]);
}

// ---------------- reducers ----------------
__global__ void reduce8_relu_h(const float* __restrict__ part,
                               const float* __restrict__ b1, __half* __restrict__ out)
{
    int idx = blockIdx.x * 256 + threadIdx.x;  // < 524288
    float s = 0.f;
#pragma unroll
    for (int z = 0; z < 8; z++) s += part[(long)z * 524288 + idx];
    s += b1[idx & 2047];
    out[idx] = __float2half_rn(fmaxf(s, 0.f));
}

__global__ void reduce_out_k(const float* __restrict__ part,
                             const float* __restrict__ bf, float* __restrict__ out)
{
    int idx = blockIdx.x * 256 + threadIdx.x;
    if (idx >= 12800) return;
    int m = idx / 50, j = idx % 50;
    float s = bf[j];
#pragma unroll
    for (int z = 0; z < 64; z++) s += part[(long)z * 16384 + m * 64 + j];
    out[idx] = s;
}

// ------------------------------------------------------------------
extern "C" void kernel_launch(void* const* d_in, const int* in_sizes, int n_in,
                              void* d_out, int out_size)
{
    const float* inputs = (const float*)d_in[0];
    const float* Wq = (const float*)d_in[1];  const float* bq = (const float*)d_in[2];
    const float* Wk = (const float*)d_in[3];  const float* bk = (const float*)d_in[4];
    const float* Wv = (const float*)d_in[5];  const float* bv = (const float*)d_in[6];
    const float* Wo = (const float*)d_in[7];  const float* bo = (const float*)d_in[8];
    const float* ln1g = (const float*)d_in[9];  const float* ln1b = (const float*)d_in[10];
    const float* W1 = (const float*)d_in[11]; const float* b1 = (const float*)d_in[12];
    const float* W2 = (const float*)d_in[13]; const float* b2 = (const float*)d_in[14];
    const float* ln2g = (const float*)d_in[15]; const float* ln2b = (const float*)d_in[16];
    const float* Wf = (const float*)d_in[17]; const float* bf = (const float*)d_in[18];
    float* out = (float*)d_out;

    __half *inh, *qkvh, *ctxh, *res1h, *xh, *hh, *v2h, *yh, *wqkvh, *woh, *wfph;
    float *bqkv, *p4, *p6;
    cudaGetSymbolAddress((void**)&inh, g_inh);
    cudaGetSymbolAddress((void**)&qkvh, g_qkvh);
    cudaGetSymbolAddress((void**)&ctxh, g_ctxh);
    cudaGetSymbolAddress((void**)&res1h, g_res1h);
    cudaGetSymbolAddress((void**)&xh, g_xh);
    cudaGetSymbolAddress((void**)&hh, g_hh);
    cudaGetSymbolAddress((void**)&v2h, g_v2h);
    cudaGetSymbolAddress((void**)&yh, g_yh);
    cudaGetSymbolAddress((void**)&wqkvh, g_wqkvh);
    cudaGetSymbolAddress((void**)&woh, g_woh);
    cudaGetSymbolAddress((void**)&wfph, g_wfph);
    cudaGetSymbolAddress((void**)&bqkv, g_bqkv);
    cudaGetSymbolAddress((void**)&p4, g_p4);
    cudaGetSymbolAddress((void**)&p6, g_p6);

    constexpr int SMF = 3 * 32768;              // 98304
    constexpr int SMW = 4 * 24576 + 2 * 8192;   // 114688
    constexpr int SMP = 4 * 12288;              // 49152
    cudaFuncSetAttribute((const void*)gemmf64<true>,
                         cudaFuncAttributeMaxDynamicSharedMemorySize, SMF);
    cudaFuncSetAttribute((const void*)gemmf64<false>,
                         cudaFuncAttributeMaxDynamicSharedMemorySize, SMF);
    cudaFuncSetAttribute((const void*)gemmw<false>,
                         cudaFuncAttributeMaxDynamicSharedMemorySize, SMW);
    cudaFuncSetAttribute((const void*)gemmw<true>,
                         cudaFuncAttributeMaxDynamicSharedMemorySize, SMW);
    cudaFuncSetAttribute((const void*)gemm16p,
                         cudaFuncAttributeMaxDynamicSharedMemorySize, SMP);

    // all prep in one launch
    prep_all<<<17414, 256>>>(Wf, wfph, inputs, inh, Wq, Wk, Wv, Wo,
                             wqkvh, woh, bq, bk, bv, bqkv);

    // fused QKV -> qkvh [16384, 1536]
    gemmf64<true><<<dim3(12, 128), 256, SMF>>>(
        inh, 512, wqkvh, 0, 32768, qkvh, 1536, 8, bqkv, nullptr);

    // MMA attention
    attn_mma<<<2048, 128>>>(qkvh, ctxh);

    // output projection + bias + residual(inputs fp32) -> res1h fp16
    gemmf64<true><<<dim3(4, 128), 256, SMF>>>(
        ctxh, 512, woh, 512, 0, res1h, 512, 8, bo, inputs);

    // LN1 -> xh
    ln512_hh<<<2048, 256>>>(res1h, xh, ln1g, ln1b);

    // h = relu(x @ W1 + b1): split-K 8 -> p4 fp32
    gemmw<false><<<dim3(16, 2, 8), 256, SMW>>>(
        xh, 32768, W1, 2048, p4, 2048, 128, 4096, 524288, nullptr, nullptr);
    reduce8_relu_h<<<2048, 256>>>(p4, b1, hh);

    // v2 = h @ W2 + b2 + xh -> v2h fp16
    gemmw<true><<<dim3(256, 2, 1), 256, SMW>>>(
        hh, 2048, W2, 32768, v2h, 32768, 64, 0, 0, b2, xh);

    // LN2 -> yh
    ln32k_hh<<<256, 1024>>>(v2h, yh, ln2g, ln2b);

    // logits: y @ wfph split-K 64 (cp.async pipelined)
    gemm16p<<<dim3(1, 2, 64), 256, SMP>>>(yh, 32768, wfph, 64, p6, 64, 16, 512, 16384);
    reduce_out_k<<<50, 256>>>(p6, bf, out);
}